// round 3
// baseline (speedup 1.0000x reference)
#include <cuda_runtime.h>
#include <cuda_bf16.h>
#include <math.h>

// Problem dims (fixed)
#define BB 8
#define LL 1024
#define EE 1024
#define HH 16
#define DD 64
#define E3 3072
#define EPS 1e-5f

// ---------------- scratch (device globals; no allocation allowed) ----------
__device__ float g_qkv[BB * LL * E3];           // (B,L,3E)   100.7 MB
__device__ float g_S[(size_t)BB * HH * LL * LL]; // (B,H,L,L) 512 MB
__device__ float g_ctx[BB * LL * EE];            // (B,L,E)    32 MB
__device__ float g_res[BB * LL * EE];            // x+attn_out 32 MB
__device__ float g_hn[BB * LL * EE];             // layernorm  32 MB
__device__ float g_avgpart[BB * HH * LL];        // per (b,h) col sums
__device__ float g_poolpart[BB * 8 * EE];        // pooled partials (8 l-chunks)

// ---------------- generic NT/NN register-tiled SGEMM -----------------------
// C[M,N] = alpha * A(M,K) * op(B) (+bias[n]) (+resid)
// BT=true : B is (N,K) row-major (C = A * B^T)
// BT=false: B is (K,N) row-major (C = A * B)
// Batched via blockIdx.z: offsets decomposed as bz = bo*inner + bi.
#define TBM 128
#define TBN 128
#define TBK 16

template <bool BT>
__global__ __launch_bounds__(256) void sgemm_kernel(
    const float* __restrict__ A, const float* __restrict__ Bp,
    float* __restrict__ C,
    const float* __restrict__ bias, const float* __restrict__ resid,
    int M, int N, int K, int lda, int ldb, int ldc,
    long long sAo, long long sAi, long long sBo, long long sBi,
    long long sCo, long long sCi, int inner, float alpha)
{
    __shared__ float As[TBK][TBM + 4];
    __shared__ float Bs[TBK][TBN + 4];

    int bz = blockIdx.z;
    int bo = bz / inner, bi = bz % inner;
    A  += bo * sAo + bi * sAi;
    Bp += bo * sBo + bi * sBi;
    long long coff = bo * sCo + bi * sCi;
    C += coff;
    if (resid) resid += coff;

    int bm = blockIdx.y * TBM;
    int bn = blockIdx.x * TBN;
    int tid = threadIdx.x;
    int tx = tid & 15, ty = tid >> 4;

    float acc[8][8];
#pragma unroll
    for (int i = 0; i < 8; i++)
#pragma unroll
        for (int j = 0; j < 8; j++) acc[i][j] = 0.f;

    for (int k0 = 0; k0 < K; k0 += TBK) {
        // Load A tile: As[k][m] = A[(bm+m)*lda + k0+k]
#pragma unroll
        for (int i = 0; i < 8; i++) {
            int idx = tid + i * 256;
            int k = idx & 15, m = idx >> 4;
            int gm = bm + m, gk = k0 + k;
            float v = 0.f;
            if (gm < M && gk < K) v = A[(long long)gm * lda + gk];
            As[k][m] = v;
        }
        // Load B tile
#pragma unroll
        for (int i = 0; i < 8; i++) {
            int idx = tid + i * 256;
            float v = 0.f;
            if (BT) {
                int k = idx & 15, n = idx >> 4;
                int gn = bn + n, gk = k0 + k;
                if (gn < N && gk < K) v = Bp[(long long)gn * ldb + gk];
                Bs[k][n] = v;
            } else {
                int n = idx & 127, k = idx >> 7;
                int gn = bn + n, gk = k0 + k;
                if (gn < N && gk < K) v = Bp[(long long)gk * ldb + gn];
                Bs[k][n] = v;
            }
        }
        __syncthreads();
#pragma unroll
        for (int kk = 0; kk < TBK; kk++) {
            float ra[8], rb[8];
#pragma unroll
            for (int i = 0; i < 8; i++) ra[i] = As[kk][ty * 8 + i];
#pragma unroll
            for (int j = 0; j < 8; j++) rb[j] = Bs[kk][tx * 8 + j];
#pragma unroll
            for (int i = 0; i < 8; i++)
#pragma unroll
                for (int j = 0; j < 8; j++) acc[i][j] += ra[i] * rb[j];
        }
        __syncthreads();
    }

#pragma unroll
    for (int i = 0; i < 8; i++) {
        int gm = bm + ty * 8 + i;
        if (gm >= M) continue;
#pragma unroll
        for (int j = 0; j < 8; j++) {
            int gn = bn + tx * 8 + j;
            if (gn >= N) continue;
            float v = acc[i][j] * alpha;
            if (bias) v += bias[gn];
            long long ci = (long long)gm * ldc + gn;
            if (resid) v += resid[ci];
            C[ci] = v;
        }
    }
}

// ---------------- block reductions -----------------------------------------
__device__ __forceinline__ float blk_reduce_sum(float v, float* sm) {
#pragma unroll
    for (int o = 16; o > 0; o >>= 1) v += __shfl_xor_sync(0xffffffffu, v, o);
    int w = threadIdx.x >> 5;
    if ((threadIdx.x & 31) == 0) sm[w] = v;
    __syncthreads();
    if (threadIdx.x == 0) {
        float s = 0.f;
        int nw = blockDim.x >> 5;
        for (int i = 0; i < nw; i++) s += sm[i];
        sm[0] = s;
    }
    __syncthreads();
    float r = sm[0];
    __syncthreads();
    return r;
}

__device__ __forceinline__ float blk_reduce_max(float v, float* sm) {
#pragma unroll
    for (int o = 16; o > 0; o >>= 1)
        v = fmaxf(v, __shfl_xor_sync(0xffffffffu, v, o));
    int w = threadIdx.x >> 5;
    if ((threadIdx.x & 31) == 0) sm[w] = v;
    __syncthreads();
    if (threadIdx.x == 0) {
        float s = sm[0];
        int nw = blockDim.x >> 5;
        for (int i = 1; i < nw; i++) s = fmaxf(s, sm[i]);
        sm[0] = s;
    }
    __syncthreads();
    float r = sm[0];
    __syncthreads();
    return r;
}

// ---------------- softmax over rows of S (in place) -------------------------
// grid = B*H*L blocks, 256 threads; row length 1024 -> float4 per thread
__global__ __launch_bounds__(256) void softmax_kernel(float* __restrict__ S) {
    __shared__ float sm[32];
    long long row = blockIdx.x;
    float* p = S + row * (long long)LL;
    float4 v = reinterpret_cast<float4*>(p)[threadIdx.x];
    float mx = fmaxf(fmaxf(v.x, v.y), fmaxf(v.z, v.w));
    mx = blk_reduce_max(mx, sm);
    v.x = __expf(v.x - mx);
    v.y = __expf(v.y - mx);
    v.z = __expf(v.z - mx);
    v.w = __expf(v.w - mx);
    float s = v.x + v.y + v.z + v.w;
    s = blk_reduce_sum(s, sm);
    float inv = 1.f / s;
    v.x *= inv; v.y *= inv; v.z *= inv; v.w *= inv;
    reinterpret_cast<float4*>(p)[threadIdx.x] = v;
}

// ---------------- avg_attn reductions ---------------------------------------
// stage 1: ap[bh][m] = sum_l S[bh][l][m];  grid (L/256, B*H)
__global__ __launch_bounds__(256) void avg_part_kernel(const float* __restrict__ S,
                                                       float* __restrict__ ap) {
    int m = blockIdx.x * 256 + threadIdx.x;
    int bh = blockIdx.y;
    const float* p = S + (long long)bh * LL * LL + m;
    float s = 0.f;
#pragma unroll 4
    for (int l = 0; l < LL; l++) s += p[(long long)l * LL];
    ap[bh * LL + m] = s;
}

// stage 2: out[b][m] = sum_h ap[b*H+h][m] / (H*L);  grid (L/256, B)
__global__ __launch_bounds__(256) void avg_final_kernel(const float* __restrict__ ap,
                                                        float* __restrict__ out) {
    int m = blockIdx.x * 256 + threadIdx.x;
    int b = blockIdx.y;
    float s = 0.f;
#pragma unroll
    for (int h = 0; h < HH; h++) s += ap[(b * HH + h) * LL + m];
    out[BB * EE + b * LL + m] = s * (1.f / (HH * (float)LL));
}

// ---------------- LayerNorm rows of g_res -> g_hn ---------------------------
// grid = B*L blocks, 256 threads (float4 per thread over E=1024)
__global__ __launch_bounds__(256) void ln_kernel(const float* __restrict__ h,
                                                 const float* __restrict__ gamma,
                                                 const float* __restrict__ beta,
                                                 float* __restrict__ hn) {
    __shared__ float sm[32];
    long long row = blockIdx.x;
    const float* p = h + row * (long long)EE;
    float4 v = reinterpret_cast<const float4*>(p)[threadIdx.x];
    float s = v.x + v.y + v.z + v.w;
    s = blk_reduce_sum(s, sm);
    float mean = s * (1.f / EE);
    float dx = v.x - mean, dy = v.y - mean, dz = v.z - mean, dw = v.w - mean;
    float sq = dx * dx + dy * dy + dz * dz + dw * dw;
    sq = blk_reduce_sum(sq, sm);
    float r = rsqrtf(sq * (1.f / EE) + EPS);
    float4 g = reinterpret_cast<const float4*>(gamma)[threadIdx.x];
    float4 bt = reinterpret_cast<const float4*>(beta)[threadIdx.x];
    float4 o;
    o.x = dx * r * g.x + bt.x;
    o.y = dy * r * g.y + bt.y;
    o.z = dz * r * g.z + bt.z;
    o.w = dw * r * g.w + bt.w;
    reinterpret_cast<float4*>(hn + row * (long long)EE)[threadIdx.x] = o;
}

// ---------------- pooled mean -----------------------------------------------
// stage 1: pp[b][lc][e] = sum over 128 l of hn;  grid (E/256, 8, B)
__global__ __launch_bounds__(256) void pooled_part_kernel(const float* __restrict__ hn,
                                                          float* __restrict__ pp) {
    int e = blockIdx.x * 256 + threadIdx.x;
    int lc = blockIdx.y;
    int b = blockIdx.z;
    const float* p = hn + ((long long)b * LL + lc * 128) * EE + e;
    float s = 0.f;
#pragma unroll 4
    for (int l = 0; l < 128; l++) s += p[(long long)l * EE];
    pp[(b * 8 + lc) * EE + e] = s;
}

// stage 2: out[b][e] = sum_lc pp / L;  grid (E/256, B)
__global__ __launch_bounds__(256) void pooled_final_kernel(const float* __restrict__ pp,
                                                           float* __restrict__ out) {
    int e = blockIdx.x * 256 + threadIdx.x;
    int b = blockIdx.y;
    float s = 0.f;
#pragma unroll
    for (int lc = 0; lc < 8; lc++) s += pp[(b * 8 + lc) * EE + e];
    out[b * EE + e] = s * (1.f / (float)LL);
}

// ---------------- launch -----------------------------------------------------
extern "C" void kernel_launch(void* const* d_in, const int* in_sizes, int n_in,
                              void* d_out, int out_size) {
    const float* x     = (const float*)d_in[0];  // (B,L,E)
    const float* w_qkv = (const float*)d_in[1];  // (3E,E)
    const float* b_qkv = (const float*)d_in[2];  // (3E)
    const float* w_out = (const float*)d_in[3];  // (E,E)
    const float* b_out = (const float*)d_in[4];  // (E)
    const float* gamma = (const float*)d_in[5];  // (E)
    const float* beta  = (const float*)d_in[6];  // (E)
    float* out = (float*)d_out;

    float *qkv, *S, *ctx, *res, *hn, *ap, *pp;
    cudaGetSymbolAddress((void**)&qkv, g_qkv);
    cudaGetSymbolAddress((void**)&S,   g_S);
    cudaGetSymbolAddress((void**)&ctx, g_ctx);
    cudaGetSymbolAddress((void**)&res, g_res);
    cudaGetSymbolAddress((void**)&hn,  g_hn);
    cudaGetSymbolAddress((void**)&ap,  g_avgpart);
    cudaGetSymbolAddress((void**)&pp,  g_poolpart);

    const int M = BB * LL;  // 8192

    // 1) QKV projection: qkv = x @ w_qkv^T + b_qkv      (8192 x 3072 x 1024)
    {
        dim3 grid(E3 / TBN, M / TBM, 1);
        sgemm_kernel<true><<<grid, 256>>>(x, w_qkv, qkv, b_qkv, nullptr,
                                          M, E3, EE, EE, EE, E3,
                                          0, 0, 0, 0, 0, 0, 1, 1.0f);
    }

    // 2) scores: S[b,h] = (Q[b,h] / sqrt(D)) @ K[b,h]^T  (1024x1024x64, 128 batches)
    {
        dim3 grid(LL / TBN, LL / TBM, BB * HH);
        sgemm_kernel<true><<<grid, 256>>>(
            qkv /*Q*/, qkv + EE /*K*/, S, nullptr, nullptr,
            LL, LL, DD, E3, E3, LL,
            (long long)LL * E3, DD,              // A: b, h offsets
            (long long)LL * E3, DD,              // B: b, h offsets
            (long long)HH * LL * LL, (long long)LL * LL,  // C: b, h offsets
            HH, 0.125f /* 1/sqrt(64) */);
    }

    // 3) softmax rows of S (in place)
    softmax_kernel<<<BB * HH * LL, 256>>>(S);

    // 4) avg_attn partials + final
    {
        dim3 g1(LL / 256, BB * HH);
        avg_part_kernel<<<g1, 256>>>(S, ap);
        dim3 g2(LL / 256, BB);
        avg_final_kernel<<<g2, 256>>>(ap, out);
    }

    // 5) ctx[b,h] = W[b,h] @ V[b,h]   (1024 x 64 x 1024, NN, 128 batches)
    {
        dim3 grid(1, LL / TBM, BB * HH);
        sgemm_kernel<false><<<grid, 256>>>(
            S, qkv + 2 * EE /*V*/, ctx, nullptr, nullptr,
            LL, DD, LL, LL, E3, EE,
            (long long)HH * LL * LL, (long long)LL * LL,  // A (=S): b, h
            (long long)LL * E3, DD,                        // B (=V): b, h
            (long long)LL * EE, DD,                        // C (=ctx): b, h
            HH, 1.0f);
    }

    // 6) out proj + bias + residual: res = ctx @ w_out^T + b_out + x
    {
        dim3 grid(EE / TBN, M / TBM, 1);
        sgemm_kernel<true><<<grid, 256>>>(ctx, w_out, res, b_out, x,
                                          M, EE, EE, EE, EE, EE,
                                          0, 0, 0, 0, 0, 0, 1, 1.0f);
    }

    // 7) layernorm rows -> hn
    ln_kernel<<<M, 256>>>(res, gamma, beta, hn);

    // 8) pooled mean
    {
        dim3 g1(EE / 256, 8, BB);
        pooled_part_kernel<<<g1, 256>>>(hn, pp);
        dim3 g2(EE / 256, BB);
        pooled_final_kernel<<<g2, 256>>>(pp, out);
    }
}

// round 5
// speedup vs baseline: 1.9066x; 1.9066x over previous
#include <cuda_runtime.h>
#include <cuda_bf16.h>
#include <math.h>
#include <stdint.h>

// Problem dims (fixed)
#define BB 8
#define LL 1024
#define EE 1024
#define HH 16
#define DD 64
#define E3 3072
#define EPS 1e-5f

// ---------------- scratch (device globals; no allocation allowed) ----------
__device__ float g_qkv[BB * LL * E3];            // (B,L,3E)   100.7 MB
__device__ float g_S[(size_t)BB * HH * LL * LL]; // (B,H,L,L)  512 MB
__device__ float g_ctx[BB * LL * EE];            // (B,L,E)    32 MB
__device__ float g_res[BB * LL * EE];            // x+attn_out 32 MB
__device__ float g_hn[BB * LL * EE];             // layernorm  32 MB
__device__ float g_avgpart[BB * HH * 8 * LL];    // per (b,h,lchunk) col sums
__device__ float g_poolpart[BB * 8 * EE];        // pooled partials

// ---------------- tf32 helpers ----------------------------------------------
__device__ __forceinline__ void f2tf2(float x, uint32_t& hi, uint32_t& lo) {
    float h, l2;
    asm("cvt.rna.tf32.f32 %0, %1;" : "=f"(h) : "f"(x));
    float l = x - h;
    asm("cvt.rna.tf32.f32 %0, %1;" : "=f"(l2) : "f"(l));
    hi = __float_as_uint(h);
    lo = __float_as_uint(l2);
}

__device__ __forceinline__ void mma8(float* d, const uint32_t* a, const uint32_t* b) {
    asm volatile(
        "mma.sync.aligned.m16n8k8.row.col.f32.tf32.tf32.f32 "
        "{%0,%1,%2,%3}, {%4,%5,%6,%7}, {%8,%9}, {%0,%1,%2,%3};"
        : "+f"(d[0]), "+f"(d[1]), "+f"(d[2]), "+f"(d[3])
        : "r"(a[0]), "r"(a[1]), "r"(a[2]), "r"(a[3]), "r"(b[0]), "r"(b[1]));
}

// ---------------- 3xTF32 tensor-core GEMM -----------------------------------
// C[M,N] = alpha * A(M,K) * op(B) (+bias[n]) (+resid)
// BT=true : B is (N,K) row-major (C = A * B^T)   -- natural for mma row.col
// BT=false: B is (K,N) row-major (C = A * B)     -- staged transposed (TN=64 only)
// Batched via blockIdx.z = bo*inner + bi.
// All tile dims assumed to divide M,N,K exactly (true for all our shapes).
template <int TN, bool BT>
__global__ __launch_bounds__(256, 1) void mma_gemm(
    const float* __restrict__ A, const float* __restrict__ Bp,
    float* __restrict__ C,
    const float* __restrict__ bias, const float* __restrict__ resid,
    int M, int N, int K, int lda, int ldb, int ldc,
    long long sAo, long long sAi, long long sBo, long long sBi,
    long long sCo, long long sCi, int inner, float alpha)
{
    static_assert(BT || TN == 64, "NN path only instantiated for TN==64");
    constexpr int TM = 128, TK = 16, SS = TK + 4;  // padded stride 20 floats
    __shared__ float As[2][TM * SS];
    __shared__ float Bs[2][TN * SS];

    int bz = blockIdx.z;
    int bo = bz / inner, bi = bz % inner;
    A  += bo * sAo + bi * sAi;
    Bp += bo * sBo + bi * sBi;
    long long coff = bo * sCo + bi * sCi;
    C += coff;
    const float* Rp = resid ? resid + coff : nullptr;

    const int bm = blockIdx.y * TM;
    const int bn = blockIdx.x * TN;
    const int tid = threadIdx.x;
    const int warp = tid >> 5, lane = tid & 31;
    const int g = lane >> 2, tg = lane & 3;

    constexpr int WN = TN / 4;      // 32 or 16
    constexpr int MT = 4;           // 64 rows per m-warp / 16
    constexpr int NTL = WN / 8;     // 4 or 2
    const int wm = (warp >> 2) * 64;
    const int wn = (warp & 3) * WN;

    float acc[MT][NTL][4];
#pragma unroll
    for (int i = 0; i < MT; i++)
#pragma unroll
        for (int j = 0; j < NTL; j++)
#pragma unroll
            for (int q = 0; q < 4; q++) acc[i][j][q] = 0.f;

    // staging coordinates
    const int ar = tid >> 2;            // 0..63
    const int ac = (tid & 3) * 4;       // 0,4,8,12
    constexpr int AIT = 2;              // 128 rows / 64
    constexpr int BIT = BT ? (TN / 64) : 0;  // 2 or 1
    const int nnN = tid & 63;           // NN path: column
    const int nnK0 = (tid >> 6) * 4;    // NN path: k start

    // ---- prologue: stage k-tile 0 into buffer 0
#pragma unroll
    for (int r = 0; r < AIT; r++) {
        int m = ar + r * 64;
        float4 v = *reinterpret_cast<const float4*>(&A[(long long)(bm + m) * lda + ac]);
        *reinterpret_cast<float4*>(&As[0][m * SS + ac]) = v;
    }
    if (BT) {
#pragma unroll
        for (int r = 0; r < (BIT ? BIT : 1); r++) {
            int n = ar + r * 64;
            if (n < TN) {
                float4 v = *reinterpret_cast<const float4*>(&Bp[(long long)(bn + n) * ldb + ac]);
                *reinterpret_cast<float4*>(&Bs[0][n * SS + ac]) = v;
            }
        }
    } else {
#pragma unroll
        for (int kk = 0; kk < 4; kk++)
            Bs[0][nnN * SS + nnK0 + kk] =
                Bp[(long long)(nnK0 + kk) * ldb + bn + nnN];
    }
    __syncthreads();

    const int nk = K / TK;
    int buf = 0;
    for (int kt = 0; kt < nk; kt++) {
        const int k0n = (kt + 1) * TK;
        const bool has_next = (kt + 1 < nk);

        // ---- issue prefetch loads for next tile
        float4 pa[AIT];
        float4 pb[2];
        float pn[4];
        if (has_next) {
#pragma unroll
            for (int r = 0; r < AIT; r++) {
                int m = ar + r * 64;
                pa[r] = *reinterpret_cast<const float4*>(
                    &A[(long long)(bm + m) * lda + k0n + ac]);
            }
            if (BT) {
#pragma unroll
                for (int r = 0; r < (BIT ? BIT : 1); r++) {
                    int n = ar + r * 64;
                    if (n < TN)
                        pb[r] = *reinterpret_cast<const float4*>(
                            &Bp[(long long)(bn + n) * ldb + k0n + ac]);
                }
            } else {
#pragma unroll
                for (int kk = 0; kk < 4; kk++)
                    pn[kk] = Bp[(long long)(k0n + nnK0 + kk) * ldb + bn + nnN];
            }
        }

        // ---- compute on current buffer
        const float* as = As[buf];
        const float* bs = Bs[buf];
#pragma unroll
        for (int ks = 0; ks < TK; ks += 8) {
            uint32_t ahi[MT][4], alo[MT][4], bhi[NTL][2], blo[NTL][2];
#pragma unroll
            for (int mt = 0; mt < MT; mt++) {
                int r0 = wm + mt * 16 + g;
                float x0 = as[r0 * SS + ks + tg];
                float x1 = as[(r0 + 8) * SS + ks + tg];
                float x2 = as[r0 * SS + ks + tg + 4];
                float x3 = as[(r0 + 8) * SS + ks + tg + 4];
                f2tf2(x0, ahi[mt][0], alo[mt][0]);
                f2tf2(x1, ahi[mt][1], alo[mt][1]);
                f2tf2(x2, ahi[mt][2], alo[mt][2]);
                f2tf2(x3, ahi[mt][3], alo[mt][3]);
            }
#pragma unroll
            for (int nt = 0; nt < NTL; nt++) {
                int c0 = wn + nt * 8 + g;
                float y0 = bs[c0 * SS + ks + tg];
                float y1 = bs[c0 * SS + ks + tg + 4];
                f2tf2(y0, bhi[nt][0], blo[nt][0]);
                f2tf2(y1, bhi[nt][1], blo[nt][1]);
            }
#pragma unroll
            for (int mt = 0; mt < MT; mt++)
#pragma unroll
                for (int nt = 0; nt < NTL; nt++) {
                    mma8(acc[mt][nt], ahi[mt], bhi[nt]);
                    mma8(acc[mt][nt], ahi[mt], blo[nt]);
                    mma8(acc[mt][nt], alo[mt], bhi[nt]);
                }
        }

        // ---- store prefetched tile into other buffer
        if (has_next) {
            int nb = buf ^ 1;
#pragma unroll
            for (int r = 0; r < AIT; r++) {
                int m = ar + r * 64;
                *reinterpret_cast<float4*>(&As[nb][m * SS + ac]) = pa[r];
            }
            if (BT) {
#pragma unroll
                for (int r = 0; r < (BIT ? BIT : 1); r++) {
                    int n = ar + r * 64;
                    if (n < TN)
                        *reinterpret_cast<float4*>(&Bs[nb][n * SS + ac]) = pb[r];
                }
            } else {
#pragma unroll
                for (int kk = 0; kk < 4; kk++)
                    Bs[nb][nnN * SS + nnK0 + kk] = pn[kk];
            }
        }
        __syncthreads();
        buf ^= 1;
    }

    // ---- epilogue
#pragma unroll
    for (int mt = 0; mt < MT; mt++) {
#pragma unroll
        for (int nt = 0; nt < NTL; nt++) {
            int c = bn + wn + nt * 8 + 2 * tg;
#pragma unroll
            for (int hrow = 0; hrow < 2; hrow++) {
                int gr = bm + wm + mt * 16 + g + hrow * 8;
                float vx = acc[mt][nt][2 * hrow] * alpha;
                float vy = acc[mt][nt][2 * hrow + 1] * alpha;
                if (bias) { vx += bias[c]; vy += bias[c + 1]; }
                long long ci = (long long)gr * ldc + c;
                if (Rp) {
                    float2 rr = *reinterpret_cast<const float2*>(&Rp[ci]);
                    vx += rr.x; vy += rr.y;
                }
                float2 o; o.x = vx; o.y = vy;
                *reinterpret_cast<float2*>(&C[ci]) = o;
            }
        }
    }
}

// ---------------- block reductions -----------------------------------------
__device__ __forceinline__ float blk_reduce_sum(float v, float* sm) {
#pragma unroll
    for (int o = 16; o > 0; o >>= 1) v += __shfl_xor_sync(0xffffffffu, v, o);
    int w = threadIdx.x >> 5;
    if ((threadIdx.x & 31) == 0) sm[w] = v;
    __syncthreads();
    if (threadIdx.x == 0) {
        float s = 0.f;
        int nw = blockDim.x >> 5;
        for (int i = 0; i < nw; i++) s += sm[i];
        sm[0] = s;
    }
    __syncthreads();
    float r = sm[0];
    __syncthreads();
    return r;
}

__device__ __forceinline__ float blk_reduce_max(float v, float* sm) {
#pragma unroll
    for (int o = 16; o > 0; o >>= 1)
        v = fmaxf(v, __shfl_xor_sync(0xffffffffu, v, o));
    int w = threadIdx.x >> 5;
    if ((threadIdx.x & 31) == 0) sm[w] = v;
    __syncthreads();
    if (threadIdx.x == 0) {
        float s = sm[0];
        int nw = blockDim.x >> 5;
        for (int i = 1; i < nw; i++) s = fmaxf(s, sm[i]);
        sm[0] = s;
    }
    __syncthreads();
    float r = sm[0];
    __syncthreads();
    return r;
}

// ---------------- softmax over rows of S (in place) -------------------------
__global__ __launch_bounds__(256) void softmax_kernel(float* __restrict__ S) {
    __shared__ float sm[32];
    long long row = blockIdx.x;
    float* p = S + row * (long long)LL;
    float4 v = reinterpret_cast<float4*>(p)[threadIdx.x];
    float mx = fmaxf(fmaxf(v.x, v.y), fmaxf(v.z, v.w));
    mx = blk_reduce_max(mx, sm);
    v.x = __expf(v.x - mx);
    v.y = __expf(v.y - mx);
    v.z = __expf(v.z - mx);
    v.w = __expf(v.w - mx);
    float s = v.x + v.y + v.z + v.w;
    s = blk_reduce_sum(s, sm);
    float inv = 1.f / s;
    v.x *= inv; v.y *= inv; v.z *= inv; v.w *= inv;
    reinterpret_cast<float4*>(p)[threadIdx.x] = v;
}

// ---------------- avg_attn reductions ---------------------------------------
// stage 1: ap[bh][lc][m] = sum over 128 l of S;  grid (L/256, 8, B*H)
__global__ __launch_bounds__(256) void avg_part_kernel(const float* __restrict__ S,
                                                       float* __restrict__ ap) {
    int m = blockIdx.x * 256 + threadIdx.x;
    int lc = blockIdx.y;
    int bh = blockIdx.z;
    const float* p = S + (long long)bh * LL * LL + (long long)lc * 128 * LL + m;
    float s = 0.f;
#pragma unroll 8
    for (int l = 0; l < 128; l++) s += p[(long long)l * LL];
    ap[(bh * 8 + lc) * LL + m] = s;
}

// stage 2: out[b][m] = sum_{h,lc} ap / (H*L);  grid (L/256, B)
__global__ __launch_bounds__(256) void avg_final_kernel(const float* __restrict__ ap,
                                                        float* __restrict__ out) {
    int m = blockIdx.x * 256 + threadIdx.x;
    int b = blockIdx.y;
    float s = 0.f;
#pragma unroll
    for (int h = 0; h < HH; h++)
#pragma unroll
        for (int lc = 0; lc < 8; lc++)
            s += ap[((b * HH + h) * 8 + lc) * LL + m];
    out[BB * EE + b * LL + m] = s * (1.f / (HH * (float)LL));
}

// ---------------- LayerNorm rows of g_res -> g_hn ---------------------------
__global__ __launch_bounds__(256) void ln_kernel(const float* __restrict__ h,
                                                 const float* __restrict__ gamma,
                                                 const float* __restrict__ beta,
                                                 float* __restrict__ hn) {
    __shared__ float sm[32];
    long long row = blockIdx.x;
    const float* p = h + row * (long long)EE;
    float4 v = reinterpret_cast<const float4*>(p)[threadIdx.x];
    float s = v.x + v.y + v.z + v.w;
    s = blk_reduce_sum(s, sm);
    float mean = s * (1.f / EE);
    float dx = v.x - mean, dy = v.y - mean, dz = v.z - mean, dw = v.w - mean;
    float sq = dx * dx + dy * dy + dz * dz + dw * dw;
    sq = blk_reduce_sum(sq, sm);
    float r = rsqrtf(sq * (1.f / EE) + EPS);
    float4 gm = reinterpret_cast<const float4*>(gamma)[threadIdx.x];
    float4 bt = reinterpret_cast<const float4*>(beta)[threadIdx.x];
    float4 o;
    o.x = dx * r * gm.x + bt.x;
    o.y = dy * r * gm.y + bt.y;
    o.z = dz * r * gm.z + bt.z;
    o.w = dw * r * gm.w + bt.w;
    reinterpret_cast<float4*>(hn + row * (long long)EE)[threadIdx.x] = o;
}

// ---------------- pooled mean -----------------------------------------------
__global__ __launch_bounds__(256) void pooled_part_kernel(const float* __restrict__ hn,
                                                          float* __restrict__ pp) {
    int e = blockIdx.x * 256 + threadIdx.x;
    int lc = blockIdx.y;
    int b = blockIdx.z;
    const float* p = hn + ((long long)b * LL + lc * 128) * EE + e;
    float s = 0.f;
#pragma unroll 8
    for (int l = 0; l < 128; l++) s += p[(long long)l * EE];
    pp[(b * 8 + lc) * EE + e] = s;
}

__global__ __launch_bounds__(256) void pooled_final_kernel(const float* __restrict__ pp,
                                                           float* __restrict__ out) {
    int e = blockIdx.x * 256 + threadIdx.x;
    int b = blockIdx.y;
    float s = 0.f;
#pragma unroll
    for (int lc = 0; lc < 8; lc++) s += pp[(b * 8 + lc) * EE + e];
    out[b * EE + e] = s * (1.f / (float)LL);
}

// ---------------- launch -----------------------------------------------------
extern "C" void kernel_launch(void* const* d_in, const int* in_sizes, int n_in,
                              void* d_out, int out_size) {
    const float* x     = (const float*)d_in[0];  // (B,L,E)
    const float* w_qkv = (const float*)d_in[1];  // (3E,E)
    const float* b_qkv = (const float*)d_in[2];  // (3E)
    const float* w_out = (const float*)d_in[3];  // (E,E)
    const float* b_out = (const float*)d_in[4];  // (E)
    const float* gamma = (const float*)d_in[5];  // (E)
    const float* beta  = (const float*)d_in[6];  // (E)
    float* out = (float*)d_out;

    float *qkv, *S, *ctx, *res, *hn, *ap, *pp;
    cudaGetSymbolAddress((void**)&qkv, g_qkv);
    cudaGetSymbolAddress((void**)&S,   g_S);
    cudaGetSymbolAddress((void**)&ctx, g_ctx);
    cudaGetSymbolAddress((void**)&res, g_res);
    cudaGetSymbolAddress((void**)&hn,  g_hn);
    cudaGetSymbolAddress((void**)&ap,  g_avgpart);
    cudaGetSymbolAddress((void**)&pp,  g_poolpart);

    const int M = BB * LL;  // 8192

    // 1) QKV projection: qkv = x @ w_qkv^T + b_qkv      (8192 x 3072 x 1024)
    {
        dim3 grid(E3 / 128, M / 128, 1);
        mma_gemm<128, true><<<grid, 256>>>(x, w_qkv, qkv, b_qkv, nullptr,
                                           M, E3, EE, EE, EE, E3,
                                           0, 0, 0, 0, 0, 0, 1, 1.0f);
    }

    // 2) scores: S[b,h] = (Q/sqrt(D)) @ K^T  (1024x1024x64, 128 batches)
    {
        dim3 grid(LL / 128, LL / 128, BB * HH);
        mma_gemm<128, true><<<grid, 256>>>(
            qkv /*Q*/, qkv + EE /*K*/, S, nullptr, nullptr,
            LL, LL, DD, E3, E3, LL,
            (long long)LL * E3, DD,
            (long long)LL * E3, DD,
            (long long)HH * LL * LL, (long long)LL * LL,
            HH, 0.125f);
    }

    // 3) softmax rows of S (in place)
    softmax_kernel<<<BB * HH * LL, 256>>>(S);

    // 4) avg_attn partials + final
    {
        dim3 g1(LL / 256, 8, BB * HH);
        avg_part_kernel<<<g1, 256>>>(S, ap);
        dim3 g2(LL / 256, BB);
        avg_final_kernel<<<g2, 256>>>(ap, out);
    }

    // 5) ctx[b,h] = W[b,h] @ V[b,h]   (1024 x 64 x 1024, NN, 128 batches)
    {
        dim3 grid(1, LL / 128, BB * HH);
        mma_gemm<64, false><<<grid, 256>>>(
            S, qkv + 2 * EE /*V*/, ctx, nullptr, nullptr,
            LL, DD, LL, LL, E3, EE,
            (long long)HH * LL * LL, (long long)LL * LL,
            (long long)LL * E3, DD,
            (long long)LL * EE, DD,
            HH, 1.0f);
    }

    // 6) out proj + bias + residual: res = ctx @ w_out^T + b_out + x
    {
        dim3 grid(EE / 128, M / 128, 1);
        mma_gemm<128, true><<<grid, 256>>>(ctx, w_out, res, b_out, x,
                                           M, EE, EE, EE, EE, EE,
                                           0, 0, 0, 0, 0, 0, 1, 1.0f);
    }

    // 7) layernorm rows -> hn
    ln_kernel<<<M, 256>>>(res, gamma, beta, hn);

    // 8) pooled mean
    {
        dim3 g1(EE / 256, 8, BB);
        pooled_part_kernel<<<g1, 256>>>(hn, pp);
        dim3 g2(EE / 256, BB);
        pooled_final_kernel<<<g2, 256>>>(pp, out);
    }
}

// round 7
// speedup vs baseline: 2.4641x; 1.2924x over previous
#include <cuda_runtime.h>
#include <cuda_bf16.h>
#include <math.h>
#include <stdint.h>

// Problem dims (fixed)
#define BB 8
#define LL 1024
#define EE 1024
#define HH 16
#define DD 64
#define E3 3072
#define EPS 1e-5f

// ---------------- scratch (device globals; no allocation allowed) ----------
__device__ float g_qkv[BB * LL * E3];            // (B,L,3E)   100.7 MB
__device__ float g_S[(size_t)BB * HH * LL * LL]; // (B,H,L,L)  512 MB
__device__ float g_ctx[BB * LL * EE];            // (B,L,E)    32 MB
__device__ float g_res[BB * LL * EE];            // x+attn_out 32 MB
__device__ float g_hn[BB * LL * EE];             // layernorm  32 MB
__device__ float g_avgpart[BB * HH * 8 * LL];    // per (b,h,lchunk) col sums
__device__ float g_poolpart[BB * 8 * EE];        // pooled partials

// ---------------- bf16 split helpers ----------------------------------------
// x = hi + lo with hi = rn_bf16(x), lo = rn_bf16(x - hi).
// Returns cell {hi_pack(bf16x2: x0 low, x1 high), lo_pack}.
__device__ __forceinline__ uint2 split2(float x0, float x1) {
    uint32_t hp, lp;
    asm("cvt.rn.bf16x2.f32 %0, %1, %2;" : "=r"(hp) : "f"(x1), "f"(x0));
    float h0 = __uint_as_float(hp << 16);
    float h1 = __uint_as_float(hp & 0xffff0000u);
    float l0 = x0 - h0;
    float l1 = x1 - h1;
    asm("cvt.rn.bf16x2.f32 %0, %1, %2;" : "=r"(lp) : "f"(l1), "f"(l0));
    return make_uint2(hp, lp);
}

__device__ __forceinline__ void mma16(float* d, const uint32_t* a, const uint32_t* b) {
    asm volatile(
        "mma.sync.aligned.m16n8k16.row.col.f32.bf16.bf16.f32 "
        "{%0,%1,%2,%3}, {%4,%5,%6,%7}, {%8,%9}, {%0,%1,%2,%3};"
        : "+f"(d[0]), "+f"(d[1]), "+f"(d[2]), "+f"(d[3])
        : "r"(a[0]), "r"(a[1]), "r"(a[2]), "r"(a[3]), "r"(b[0]), "r"(b[1]));
}

// ---------------- 3x-bf16-split tensor-core GEMM -----------------------------
// C[M,N] = alpha * A(M,K) * op(B) (+bias[n]) (+resid)
// BT=true : B is (N,K) row-major (C = A * B^T)
// BT=false: B is (K,N) row-major (C = A * B)   (TN=64 only)
// Batched via blockIdx.z = bo*inner + bi. Tile dims divide M,N,K exactly.
// acc += hi*hi + hi*lo + lo*hi  (lo*lo term negligible: ~2^-18 relative)
template <int TN, bool BT>
__global__ __launch_bounds__(256, 1) void mma_gemm(
    const float* __restrict__ A, const float* __restrict__ Bp,
    float* __restrict__ C,
    const float* __restrict__ bias, const float* __restrict__ resid,
    int M, int N, int K, int lda, int ldb, int ldc,
    long long sAo, long long sAi, long long sBo, long long sBi,
    long long sCo, long long sCi, int inner, float alpha)
{
    static_assert(BT || TN == 64, "NN path only instantiated for TN==64");
    constexpr int TM = 128, TK = 16;
    constexpr int KPS = 12;  // 8 k-pair cells + 4 pad (u64 cells) -> conflict-free
    __shared__ uint2 As[2][TM * KPS];
    __shared__ uint2 Bs[2][TN * KPS];

    int bz = blockIdx.z;
    int bo = bz / inner, bi = bz % inner;
    A  += bo * sAo + bi * sAi;
    Bp += bo * sBo + bi * sBi;
    long long coff = bo * sCo + bi * sCi;
    C += coff;
    const float* Rp = resid ? resid + coff : nullptr;

    const int bm = blockIdx.y * TM;
    const int bn = blockIdx.x * TN;
    const int tid = threadIdx.x;
    const int warp = tid >> 5, lane = tid & 31;
    const int g = lane >> 2, tg = lane & 3;

    constexpr int WN = TN / 4;       // 32 or 16
    constexpr int MT = 4;            // 4 m16 tiles -> 64 rows per m-warp-group
    constexpr int NTL = WN / 8;      // 4 or 2
    const int wm = (warp >> 2) * 64;
    const int wn = (warp & 3) * WN;

    float acc[MT][NTL][4];
#pragma unroll
    for (int i = 0; i < MT; i++)
#pragma unroll
        for (int j = 0; j < NTL; j++)
#pragma unroll
            for (int q = 0; q < 4; q++) acc[i][j][q] = 0.f;

    // staging coordinates
    const int ar  = tid >> 2;          // 0..63 (row)
    const int ac  = (tid & 3) * 4;     // k offset 0,4,8,12
    const int kpb = ac >> 1;           // cell index base
    constexpr int AIT = 2;             // 128 rows / 64
    constexpr int BIT = BT ? (TN / 64) : 1;
    const int nnN  = tid & 63;         // NN path: column
    const int nnK0 = (tid >> 6) * 4;   // NN path: k start

    // ---- prologue: stage k-tile 0 into buffer 0
#pragma unroll
    for (int r = 0; r < AIT; r++) {
        int m = ar + r * 64;
        float4 v = *reinterpret_cast<const float4*>(&A[(long long)(bm + m) * lda + ac]);
        As[0][m * KPS + kpb]     = split2(v.x, v.y);
        As[0][m * KPS + kpb + 1] = split2(v.z, v.w);
    }
    if (BT) {
#pragma unroll
        for (int r = 0; r < BIT; r++) {
            int n = ar + r * 64;
            if (n < TN) {
                float4 v = *reinterpret_cast<const float4*>(&Bp[(long long)(bn + n) * ldb + ac]);
                Bs[0][n * KPS + kpb]     = split2(v.x, v.y);
                Bs[0][n * KPS + kpb + 1] = split2(v.z, v.w);
            }
        }
    } else {
        float p0 = Bp[(long long)(nnK0 + 0) * ldb + bn + nnN];
        float p1 = Bp[(long long)(nnK0 + 1) * ldb + bn + nnN];
        float p2 = Bp[(long long)(nnK0 + 2) * ldb + bn + nnN];
        float p3 = Bp[(long long)(nnK0 + 3) * ldb + bn + nnN];
        Bs[0][nnN * KPS + (nnK0 >> 1)]     = split2(p0, p1);
        Bs[0][nnN * KPS + (nnK0 >> 1) + 1] = split2(p2, p3);
    }
    __syncthreads();

    const int nk = K / TK;
    int buf = 0;
    for (int kt = 0; kt < nk; kt++) {
        const int k0n = (kt + 1) * TK;
        const bool has_next = (kt + 1 < nk);

        // ---- issue prefetch loads for next tile
        float4 pa[AIT];
        float4 pb[2];
        float pn[4];
        if (has_next) {
#pragma unroll
            for (int r = 0; r < AIT; r++) {
                int m = ar + r * 64;
                pa[r] = *reinterpret_cast<const float4*>(
                    &A[(long long)(bm + m) * lda + k0n + ac]);
            }
            if (BT) {
#pragma unroll
                for (int r = 0; r < BIT; r++) {
                    int n = ar + r * 64;
                    if (n < TN)
                        pb[r] = *reinterpret_cast<const float4*>(
                            &Bp[(long long)(bn + n) * ldb + k0n + ac]);
                }
            } else {
#pragma unroll
                for (int kk = 0; kk < 4; kk++)
                    pn[kk] = Bp[(long long)(k0n + nnK0 + kk) * ldb + bn + nnN];
            }
        }

        // ---- compute on current buffer (one k16 slice per tile)
        {
            const uint2* as = As[buf];
            const uint2* bs = Bs[buf];
            uint2 afr[MT][4];
            uint2 bfr[NTL][2];
#pragma unroll
            for (int mt = 0; mt < MT; mt++) {
                int r0 = wm + mt * 16 + g;
                afr[mt][0] = as[r0 * KPS + tg];
                afr[mt][1] = as[(r0 + 8) * KPS + tg];
                afr[mt][2] = as[r0 * KPS + tg + 4];
                afr[mt][3] = as[(r0 + 8) * KPS + tg + 4];
            }
#pragma unroll
            for (int nt = 0; nt < NTL; nt++) {
                int c0 = wn + nt * 8 + g;
                bfr[nt][0] = bs[c0 * KPS + tg];
                bfr[nt][1] = bs[c0 * KPS + tg + 4];
            }
#pragma unroll
            for (int mt = 0; mt < MT; mt++) {
                uint32_t ah[4] = {afr[mt][0].x, afr[mt][1].x, afr[mt][2].x, afr[mt][3].x};
                uint32_t al[4] = {afr[mt][0].y, afr[mt][1].y, afr[mt][2].y, afr[mt][3].y};
#pragma unroll
                for (int nt = 0; nt < NTL; nt++) {
                    uint32_t bh[2] = {bfr[nt][0].x, bfr[nt][1].x};
                    uint32_t bl[2] = {bfr[nt][0].y, bfr[nt][1].y};
                    mma16(acc[mt][nt], ah, bh);
                    mma16(acc[mt][nt], ah, bl);
                    mma16(acc[mt][nt], al, bh);
                }
            }
        }

        // ---- convert+store prefetched tile into other buffer
        if (has_next) {
            int nb = buf ^ 1;
#pragma unroll
            for (int r = 0; r < AIT; r++) {
                int m = ar + r * 64;
                As[nb][m * KPS + kpb]     = split2(pa[r].x, pa[r].y);
                As[nb][m * KPS + kpb + 1] = split2(pa[r].z, pa[r].w);
            }
            if (BT) {
#pragma unroll
                for (int r = 0; r < BIT; r++) {
                    int n = ar + r * 64;
                    if (n < TN) {
                        Bs[nb][n * KPS + kpb]     = split2(pb[r].x, pb[r].y);
                        Bs[nb][n * KPS + kpb + 1] = split2(pb[r].z, pb[r].w);
                    }
                }
            } else {
                Bs[nb][nnN * KPS + (nnK0 >> 1)]     = split2(pn[0], pn[1]);
                Bs[nb][nnN * KPS + (nnK0 >> 1) + 1] = split2(pn[2], pn[3]);
            }
        }
        __syncthreads();
        buf ^= 1;
    }

    // ---- epilogue (same D-fragment layout as m16n8k8)
#pragma unroll
    for (int mt = 0; mt < MT; mt++) {
#pragma unroll
        for (int nt = 0; nt < NTL; nt++) {
            int c = bn + wn + nt * 8 + 2 * tg;
#pragma unroll
            for (int hrow = 0; hrow < 2; hrow++) {
                int gr = bm + wm + mt * 16 + g + hrow * 8;
                float vx = acc[mt][nt][2 * hrow] * alpha;
                float vy = acc[mt][nt][2 * hrow + 1] * alpha;
                if (bias) { vx += bias[c]; vy += bias[c + 1]; }
                long long ci = (long long)gr * ldc + c;
                if (Rp) {
                    float2 rr = *reinterpret_cast<const float2*>(&Rp[ci]);
                    vx += rr.x; vy += rr.y;
                }
                float2 o; o.x = vx; o.y = vy;
                *reinterpret_cast<float2*>(&C[ci]) = o;
            }
        }
    }
}

// ---------------- block reductions -----------------------------------------
__device__ __forceinline__ float blk_reduce_sum(float v, float* sm) {
#pragma unroll
    for (int o = 16; o > 0; o >>= 1) v += __shfl_xor_sync(0xffffffffu, v, o);
    int w = threadIdx.x >> 5;
    if ((threadIdx.x & 31) == 0) sm[w] = v;
    __syncthreads();
    if (threadIdx.x == 0) {
        float s = 0.f;
        int nw = blockDim.x >> 5;
        for (int i = 0; i < nw; i++) s += sm[i];
        sm[0] = s;
    }
    __syncthreads();
    float r = sm[0];
    __syncthreads();
    return r;
}

__device__ __forceinline__ float blk_reduce_max(float v, float* sm) {
#pragma unroll
    for (int o = 16; o > 0; o >>= 1)
        v = fmaxf(v, __shfl_xor_sync(0xffffffffu, v, o));
    int w = threadIdx.x >> 5;
    if ((threadIdx.x & 31) == 0) sm[w] = v;
    __syncthreads();
    if (threadIdx.x == 0) {
        float s = sm[0];
        int nw = blockDim.x >> 5;
        for (int i = 1; i < nw; i++) s = fmaxf(s, sm[i]);
        sm[0] = s;
    }
    __syncthreads();
    float r = sm[0];
    __syncthreads();
    return r;
}

// ---------------- softmax over rows of S (in place) -------------------------
__global__ __launch_bounds__(256) void softmax_kernel(float* __restrict__ S) {
    __shared__ float sm[32];
    long long row = blockIdx.x;
    float* p = S + row * (long long)LL;
    float4 v = reinterpret_cast<float4*>(p)[threadIdx.x];
    float mx = fmaxf(fmaxf(v.x, v.y), fmaxf(v.z, v.w));
    mx = blk_reduce_max(mx, sm);
    v.x = __expf(v.x - mx);
    v.y = __expf(v.y - mx);
    v.z = __expf(v.z - mx);
    v.w = __expf(v.w - mx);
    float s = v.x + v.y + v.z + v.w;
    s = blk_reduce_sum(s, sm);
    float inv = 1.f / s;
    v.x *= inv; v.y *= inv; v.z *= inv; v.w *= inv;
    reinterpret_cast<float4*>(p)[threadIdx.x] = v;
}

// ---------------- avg_attn reductions ---------------------------------------
__global__ __launch_bounds__(256) void avg_part_kernel(const float* __restrict__ S,
                                                       float* __restrict__ ap) {
    int m = blockIdx.x * 256 + threadIdx.x;
    int lc = blockIdx.y;
    int bh = blockIdx.z;
    const float* p = S + (long long)bh * LL * LL + (long long)lc * 128 * LL + m;
    float s = 0.f;
#pragma unroll 8
    for (int l = 0; l < 128; l++) s += p[(long long)l * LL];
    ap[(bh * 8 + lc) * LL + m] = s;
}

__global__ __launch_bounds__(256) void avg_final_kernel(const float* __restrict__ ap,
                                                        float* __restrict__ out) {
    int m = blockIdx.x * 256 + threadIdx.x;
    int b = blockIdx.y;
    float s = 0.f;
#pragma unroll
    for (int h = 0; h < HH; h++)
#pragma unroll
        for (int lc = 0; lc < 8; lc++)
            s += ap[((b * HH + h) * 8 + lc) * LL + m];
    out[BB * EE + b * LL + m] = s * (1.f / (HH * (float)LL));
}

// ---------------- LayerNorm rows of g_res -> g_hn ---------------------------
__global__ __launch_bounds__(256) void ln_kernel(const float* __restrict__ h,
                                                 const float* __restrict__ gamma,
                                                 const float* __restrict__ beta,
                                                 float* __restrict__ hn) {
    __shared__ float sm[32];
    long long row = blockIdx.x;
    const float* p = h + row * (long long)EE;
    float4 v = reinterpret_cast<const float4*>(p)[threadIdx.x];
    float s = v.x + v.y + v.z + v.w;
    s = blk_reduce_sum(s, sm);
    float mean = s * (1.f / EE);
    float dx = v.x - mean, dy = v.y - mean, dz = v.z - mean, dw = v.w - mean;
    float sq = dx * dx + dy * dy + dz * dz + dw * dw;
    sq = blk_reduce_sum(sq, sm);
    float r = rsqrtf(sq * (1.f / EE) + EPS);
    float4 gm = reinterpret_cast<const float4*>(gamma)[threadIdx.x];
    float4 bt = reinterpret_cast<const float4*>(beta)[threadIdx.x];
    float4 o;
    o.x = dx * r * gm.x + bt.x;
    o.y = dy * r * gm.y + bt.y;
    o.z = dz * r * gm.z + bt.z;
    o.w = dw * r * gm.w + bt.w;
    reinterpret_cast<float4*>(hn + row * (long long)EE)[threadIdx.x] = o;
}

// ---------------- pooled mean -----------------------------------------------
__global__ __launch_bounds__(256) void pooled_part_kernel(const float* __restrict__ hn,
                                                          float* __restrict__ pp) {
    int e = blockIdx.x * 256 + threadIdx.x;
    int lc = blockIdx.y;
    int b = blockIdx.z;
    const float* p = hn + ((long long)b * LL + lc * 128) * EE + e;
    float s = 0.f;
#pragma unroll 8
    for (int l = 0; l < 128; l++) s += p[(long long)l * EE];
    pp[(b * 8 + lc) * EE + e] = s;
}

__global__ __launch_bounds__(256) void pooled_final_kernel(const float* __restrict__ pp,
                                                           float* __restrict__ out) {
    int e = blockIdx.x * 256 + threadIdx.x;
    int b = blockIdx.y;
    float s = 0.f;
#pragma unroll
    for (int lc = 0; lc < 8; lc++) s += pp[(b * 8 + lc) * EE + e];
    out[b * EE + e] = s * (1.f / (float)LL);
}

// ---------------- launch -----------------------------------------------------
extern "C" void kernel_launch(void* const* d_in, const int* in_sizes, int n_in,
                              void* d_out, int out_size) {
    const float* x     = (const float*)d_in[0];  // (B,L,E)
    const float* w_qkv = (const float*)d_in[1];  // (3E,E)
    const float* b_qkv = (const float*)d_in[2];  // (3E)
    const float* w_out = (const float*)d_in[3];  // (E,E)
    const float* b_out = (const float*)d_in[4];  // (E)
    const float* gamma = (const float*)d_in[5];  // (E)
    const float* beta  = (const float*)d_in[6];  // (E)
    float* out = (float*)d_out;

    float *qkv, *S, *ctx, *res, *hn, *ap, *pp;
    cudaGetSymbolAddress((void**)&qkv, g_qkv);
    cudaGetSymbolAddress((void**)&S,   g_S);
    cudaGetSymbolAddress((void**)&ctx, g_ctx);
    cudaGetSymbolAddress((void**)&res, g_res);
    cudaGetSymbolAddress((void**)&hn,  g_hn);
    cudaGetSymbolAddress((void**)&ap,  g_avgpart);
    cudaGetSymbolAddress((void**)&pp,  g_poolpart);

    const int M = BB * LL;  // 8192

    // 1) QKV projection: qkv = x @ w_qkv^T + b_qkv      (8192 x 3072 x 1024)
    {
        dim3 grid(E3 / 128, M / 128, 1);
        mma_gemm<128, true><<<grid, 256>>>(x, w_qkv, qkv, b_qkv, nullptr,
                                           M, E3, EE, EE, EE, E3,
                                           0, 0, 0, 0, 0, 0, 1, 1.0f);
    }

    // 2) scores: S[b,h] = (Q/sqrt(D)) @ K^T  (1024x1024x64, 128 batches)
    {
        dim3 grid(LL / 128, LL / 128, BB * HH);
        mma_gemm<128, true><<<grid, 256>>>(
            qkv /*Q*/, qkv + EE /*K*/, S, nullptr, nullptr,
            LL, LL, DD, E3, E3, LL,
            (long long)LL * E3, DD,
            (long long)LL * E3, DD,
            (long long)HH * LL * LL, (long long)LL * LL,
            HH, 0.125f);
    }

    // 3) softmax rows of S (in place)
    softmax_kernel<<<BB * HH * LL, 256>>>(S);

    // 4) avg_attn partials + final
    {
        dim3 g1(LL / 256, 8, BB * HH);
        avg_part_kernel<<<g1, 256>>>(S, ap);
        dim3 g2(LL / 256, BB);
        avg_final_kernel<<<g2, 256>>>(ap, out);
    }

    // 5) ctx[b,h] = W[b,h] @ V[b,h]   (1024 x 64 x 1024, NN, 128 batches)
    {
        dim3 grid(1, LL / 128, BB * HH);
        mma_gemm<64, false><<<grid, 256>>>(
            S, qkv + 2 * EE /*V*/, ctx, nullptr, nullptr,
            LL, DD, LL, LL, E3, EE,
            (long long)HH * LL * LL, (long long)LL * LL,
            (long long)LL * E3, DD,
            (long long)LL * EE, DD,
            HH, 1.0f);
    }

    // 6) out proj + bias + residual: res = ctx @ w_out^T + b_out + x
    {
        dim3 grid(EE / 128, M / 128, 1);
        mma_gemm<128, true><<<grid, 256>>>(ctx, w_out, res, b_out, x,
                                           M, EE, EE, EE, EE, EE,
                                           0, 0, 0, 0, 0, 0, 1, 1.0f);
    }

    // 7) layernorm rows -> hn
    ln_kernel<<<M, 256>>>(res, gamma, beta, hn);

    // 8) pooled mean
    {
        dim3 g1(EE / 256, 8, BB);
        pooled_part_kernel<<<g1, 256>>>(hn, pp);
        dim3 g2(EE / 256, BB);
        pooled_final_kernel<<<g2, 256>>>(pp, out);
    }
}

// round 10
// speedup vs baseline: 2.9247x; 1.1869x over previous
#include <cuda_runtime.h>
#include <cuda_bf16.h>
#include <math.h>
#include <stdint.h>

// Problem dims (fixed)
#define BB 8
#define LL 1024
#define EE 1024
#define HH 16
#define DD 64
#define E3 3072
#define EPS 1e-5f

// ---------------- scratch (device globals; no allocation allowed) ----------
// "cell" = uint2 {hi_bf16x2, lo_bf16x2} for a pair of consecutive-K fp32 values.
__device__ __align__(128) uint2 g_qkvc[BB * LL * E3 / 2];               // 100 MB
__device__ float g_S[(size_t)BB * HH * LL * LL];                         // 512 MB
__device__ __align__(128) unsigned g_wb[(size_t)BB * HH * LL * LL / 2];  // W bf16 hi, 256 MB
__device__ __align__(128) uint2 g_vtc[BB * HH * DD * LL / 2];            // Vt cells, 32 MB
__device__ __align__(128) uint2 g_ctxc[BB * LL * EE / 2];                // ctx cells, 32 MB
__device__ __align__(128) uint2 g_xc[BB * LL * EE / 2];                  // x cells, 32 MB
__device__ __align__(128) uint2 g_wqc[E3 * EE / 2];                      // w_qkv cells, 12 MB
__device__ __align__(128) uint2 g_woc[EE * EE / 2];                      // w_out cells, 4 MB
__device__ float g_res[BB * LL * EE];                                    // 32 MB
__device__ float g_hn[BB * LL * EE];                                     // 32 MB
__device__ float g_avgpart[BB * HH * 8 * LL];
__device__ float g_poolpart[BB * 8 * EE];

// ---------------- helpers ----------------------------------------------------
__device__ __forceinline__ uint2 split2(float x0, float x1) {
    uint32_t hp, lp;
    asm("cvt.rn.bf16x2.f32 %0, %1, %2;" : "=r"(hp) : "f"(x1), "f"(x0));
    float h0 = __uint_as_float(hp << 16);
    float h1 = __uint_as_float(hp & 0xffff0000u);
    float l0 = x0 - h0;
    float l1 = x1 - h1;
    asm("cvt.rn.bf16x2.f32 %0, %1, %2;" : "=r"(lp) : "f"(l1), "f"(l0));
    return make_uint2(hp, lp);
}

__device__ __forceinline__ void mma16(float* d, const uint32_t* a, const uint32_t* b) {
    asm volatile(
        "mma.sync.aligned.m16n8k16.row.col.f32.bf16.bf16.f32 "
        "{%0,%1,%2,%3}, {%4,%5,%6,%7}, {%8,%9}, {%0,%1,%2,%3};"
        : "+f"(d[0]), "+f"(d[1]), "+f"(d[2]), "+f"(d[3])
        : "r"(a[0]), "r"(a[1]), "r"(a[2]), "r"(a[3]), "r"(b[0]), "r"(b[1]));
}

__device__ __forceinline__ void cp16(uint32_t dst, const void* src) {
    asm volatile("cp.async.cg.shared.global [%0], [%1], 16;"
                 :: "r"(dst), "l"(__cvta_generic_to_global(src)) : "memory");
}
__device__ __forceinline__ void cp_commit() {
    asm volatile("cp.async.commit_group;" ::: "memory");
}
template <int N>
__device__ __forceinline__ void cp_wait() {
    asm volatile("cp.async.wait_group %0;" :: "n"(N) : "memory");
}

// ---------------- pre-split kernel: fp32 -> cells ----------------------------
__global__ __launch_bounds__(256) void split_kernel(const float2* __restrict__ src,
                                                    uint2* __restrict__ dst, int n) {
    int i = blockIdx.x * 256 + threadIdx.x;
    int stride = gridDim.x * 256;
    for (; i < n; i += stride) {
        float2 v = src[i];
        dst[i] = split2(v.x, v.y);
    }
}

// ---------------- cp.async bf16-cell tensor-core GEMM ------------------------
// C[128*gy, TN*gx] = alpha * A(M,K) * B(N,K)^T (+bias) (+resid)
// A: ASPLIT ? uint2 cells (3-term) : uint hi-cells (2-term). B: uint2 cells.
// ld*C in cells (= K_fp32/2). OUTC: write C as split cells (else fp32).
// Batched via blockIdx.z = bo*inner + bi (A/B strides in cells, C in fp32).
template <int TN, bool ASPLIT, bool OUTC>
__global__ __launch_bounds__(256, 1) void cgemm(
    const void* __restrict__ Ap_, const uint2* __restrict__ Bp,
    float* __restrict__ C,
    const float* __restrict__ bias, const float* __restrict__ resid,
    int K, int ldaC, int ldbC, int ldc,
    long long sAo, long long sAi, long long sBo, long long sBi,
    long long sCo, long long sCi, int inner, float alpha)
{
    extern __shared__ __align__(16) char sm[];
    constexpr int KPS = 12;                        // 8 cells + 4 pad
    constexpr int ABYTES = ASPLIT ? 128 * KPS * 8 : 128 * KPS * 4;
    constexpr int BBYTES = TN * KPS * 8;

    const int tid = threadIdx.x;
    const int warp = tid >> 5, lane = tid & 31;
    const int g = lane >> 2, tg = lane & 3;

    int bz = blockIdx.z;
    int bo = bz / inner, bi = bz % inner;
    long long aoff = bo * sAo + bi * sAi;
    const uint2* A2 = (const uint2*)Ap_ + aoff;
    const unsigned* A1 = (const unsigned*)Ap_ + aoff;
    Bp += bo * sBo + bi * sBi;
    long long coff = bo * sCo + bi * sCi;
    C += coff;
    const float* Rp = resid ? resid + coff : nullptr;

    const int bm = blockIdx.y * 128;
    const int bn = blockIdx.x * TN;

    constexpr int WN = TN / 4;        // 32 or 16
    constexpr int MT = 4;
    constexpr int NTL = WN / 8;       // 4 or 2
    const int wm = (warp >> 2) * 64;
    const int wn = (warp & 3) * WN;

    float acc[MT][NTL][4];
#pragma unroll
    for (int i = 0; i < MT; i++)
#pragma unroll
        for (int j = 0; j < NTL; j++)
#pragma unroll
            for (int q = 0; q < 4; q++) acc[i][j][q] = 0.f;

    uint32_t sb;
    asm("{ .reg .u64 t; cvta.to.shared.u64 t, %1; cvt.u32.u64 %0, t; }"
        : "=r"(sb) : "l"(sm));

    const int nc = K / 16;

    // ---- async staging of K16 chunk c into stage s
    auto stage = [&](int c, int s) {
        uint32_t aBase = sb + s * ABYTES;
        uint32_t bBase = sb + 2 * ABYTES + s * BBYTES;
        if (ASPLIT) {
            int r0 = tid >> 2, j = tid & 3;     // 64 rows/pass, 4 x 16B chunks/row
#pragma unroll
            for (int p = 0; p < 2; p++) {
                int row = r0 + 64 * p;
                const uint2* src = A2 + (long long)(bm + row) * ldaC + c * 8 + 2 * j;
                cp16(aBase + row * (KPS * 8) + 16 * j, src);
            }
        } else {
            int row = tid >> 1, j = tid & 1;    // 128 rows, 2 x 16B chunks/row
            const unsigned* src = A1 + (long long)(bm + row) * ldaC + c * 8 + 4 * j;
            cp16(aBase + row * (KPS * 4) + 16 * j, src);
        }
        {
            int r0 = tid >> 2, j = tid & 3;
#pragma unroll
            for (int p = 0; p < TN / 64; p++) {
                int row = r0 + 64 * p;
                const uint2* src = Bp + (long long)(bn + row) * ldbC + c * 8 + 2 * j;
                cp16(bBase + row * (KPS * 8) + 16 * j, src);
            }
        }
    };

    stage(0, 0);
    cp_commit();

    for (int c = 0; c < nc; c++) {
        const int buf = c & 1;
        const bool has_next = (c + 1 < nc);
        if (has_next) { stage(c + 1, buf ^ 1); cp_commit(); cp_wait<1>(); }
        else          { cp_wait<0>(); }
        __syncthreads();

        const uint2* bs = (const uint2*)(sm + 2 * ABYTES + buf * BBYTES);
        uint2 bfr[NTL][2];
#pragma unroll
        for (int nt = 0; nt < NTL; nt++) {
            int c0 = wn + nt * 8 + g;
            bfr[nt][0] = bs[c0 * KPS + tg];
            bfr[nt][1] = bs[c0 * KPS + tg + 4];
        }

        if (ASPLIT) {
            const uint2* as = (const uint2*)(sm + buf * ABYTES);
#pragma unroll
            for (int mt = 0; mt < MT; mt++) {
                int r0 = wm + mt * 16 + g;
                uint2 f0 = as[r0 * KPS + tg];
                uint2 f1 = as[(r0 + 8) * KPS + tg];
                uint2 f2 = as[r0 * KPS + tg + 4];
                uint2 f3 = as[(r0 + 8) * KPS + tg + 4];
                uint32_t ah[4] = {f0.x, f1.x, f2.x, f3.x};
                uint32_t al[4] = {f0.y, f1.y, f2.y, f3.y};
#pragma unroll
                for (int nt = 0; nt < NTL; nt++) {
                    uint32_t bh[2] = {bfr[nt][0].x, bfr[nt][1].x};
                    uint32_t bl[2] = {bfr[nt][0].y, bfr[nt][1].y};
                    mma16(acc[mt][nt], ah, bh);
                    mma16(acc[mt][nt], ah, bl);
                    mma16(acc[mt][nt], al, bh);
                }
            }
        } else {
            const unsigned* as = (const unsigned*)(sm + buf * ABYTES);
#pragma unroll
            for (int mt = 0; mt < MT; mt++) {
                int r0 = wm + mt * 16 + g;
                uint32_t ah[4];
                ah[0] = as[r0 * KPS + tg];
                ah[1] = as[(r0 + 8) * KPS + tg];
                ah[2] = as[r0 * KPS + tg + 4];
                ah[3] = as[(r0 + 8) * KPS + tg + 4];
#pragma unroll
                for (int nt = 0; nt < NTL; nt++) {
                    uint32_t bh[2] = {bfr[nt][0].x, bfr[nt][1].x};
                    uint32_t bl[2] = {bfr[nt][0].y, bfr[nt][1].y};
                    mma16(acc[mt][nt], ah, bh);
                    mma16(acc[mt][nt], ah, bl);
                }
            }
        }
        __syncthreads();
    }

    // ---- epilogue
#pragma unroll
    for (int mt = 0; mt < MT; mt++) {
#pragma unroll
        for (int nt = 0; nt < NTL; nt++) {
            int c = bn + wn + nt * 8 + 2 * tg;
#pragma unroll
            for (int hrow = 0; hrow < 2; hrow++) {
                int gr = bm + wm + mt * 16 + g + hrow * 8;
                float vx = acc[mt][nt][2 * hrow] * alpha;
                float vy = acc[mt][nt][2 * hrow + 1] * alpha;
                if (bias) { vx += bias[c]; vy += bias[c + 1]; }
                long long ci = (long long)gr * ldc + c;
                if (Rp) {
                    float2 rr = *reinterpret_cast<const float2*>(&Rp[ci]);
                    vx += rr.x; vy += rr.y;
                }
                if (OUTC) {
                    reinterpret_cast<uint2*>(C)[ci >> 1] = split2(vx, vy);
                } else {
                    float2 o; o.x = vx; o.y = vy;
                    *reinterpret_cast<float2*>(&C[ci]) = o;
                }
            }
        }
    }
}

// ---------------- V transpose (cells -> transposed cells) --------------------
__global__ __launch_bounds__(256) void vtrans_kernel(const uint2* __restrict__ qc,
                                                     uint2* __restrict__ vt) {
    __shared__ ushort hiS[32][33];
    __shared__ ushort loS[32][33];
    int bh = blockIdx.z;
    int b = bh >> 4, h = bh & 15;
    int lb = blockIdx.x * 32, db = blockIdx.y * 32;
    int t = threadIdx.x;
    int l = t >> 3, cj = t & 7;
#pragma unroll
    for (int p = 0; p < 2; p++) {
        int j = cj + 8 * p;  // local d-cell 0..15
        long long idx = (long long)(b * LL + lb + l) * (E3 / 2) + 1024 + h * 32 + (db >> 1) + j;
        uint2 cell = qc[idx];
        hiS[l][2 * j]     = (ushort)(cell.x & 0xffffu);
        hiS[l][2 * j + 1] = (ushort)(cell.x >> 16);
        loS[l][2 * j]     = (ushort)(cell.y & 0xffffu);
        loS[l][2 * j + 1] = (ushort)(cell.y >> 16);
    }
    __syncthreads();
    int d = t >> 3;
#pragma unroll
    for (int p = 0; p < 2; p++) {
        int jj = cj + 8 * p;  // local l-pair 0..15
        uint2 cell;
        cell.x = (uint32_t)hiS[2 * jj][d] | ((uint32_t)hiS[2 * jj + 1][d] << 16);
        cell.y = (uint32_t)loS[2 * jj][d] | ((uint32_t)loS[2 * jj + 1][d] << 16);
        long long dst = (long long)bh * (DD * LL / 2) + (long long)(db + d) * (LL / 2) + (lb >> 1) + jj;
        vt[dst] = cell;
    }
}

// ---------------- block reductions -----------------------------------------
__device__ __forceinline__ float blk_reduce_sum(float v, float* sm) {
#pragma unroll
    for (int o = 16; o > 0; o >>= 1) v += __shfl_xor_sync(0xffffffffu, v, o);
    int w = threadIdx.x >> 5;
    if ((threadIdx.x & 31) == 0) sm[w] = v;
    __syncthreads();
    if (threadIdx.x == 0) {
        float s = 0.f;
        int nw = blockDim.x >> 5;
        for (int i = 0; i < nw; i++) s += sm[i];
        sm[0] = s;
    }
    __syncthreads();
    float r = sm[0];
    __syncthreads();
    return r;
}

__device__ __forceinline__ float blk_reduce_max(float v, float* sm) {
#pragma unroll
    for (int o = 16; o > 0; o >>= 1)
        v = fmaxf(v, __shfl_xor_sync(0xffffffffu, v, o));
    int w = threadIdx.x >> 5;
    if ((threadIdx.x & 31) == 0) sm[w] = v;
    __syncthreads();
    if (threadIdx.x == 0) {
        float s = sm[0];
        int nw = blockDim.x >> 5;
        for (int i = 1; i < nw; i++) s = fmaxf(s, sm[i]);
        sm[0] = s;
    }
    __syncthreads();
    float r = sm[0];
    __syncthreads();
    return r;
}

// ---------------- softmax: read S fp32, write W bf16 (hi only) ---------------
__global__ __launch_bounds__(256) void softmax_kernel(const float* __restrict__ S,
                                                      unsigned* __restrict__ Wb) {
    __shared__ float sm[32];
    long long row = blockIdx.x;
    const float* p = S + row * (long long)LL;
    float4 v = reinterpret_cast<const float4*>(p)[threadIdx.x];
    float mx = fmaxf(fmaxf(v.x, v.y), fmaxf(v.z, v.w));
    mx = blk_reduce_max(mx, sm);
    v.x = __expf(v.x - mx);
    v.y = __expf(v.y - mx);
    v.z = __expf(v.z - mx);
    v.w = __expf(v.w - mx);
    float s = v.x + v.y + v.z + v.w;
    s = blk_reduce_sum(s, sm);
    float inv = 1.f / s;
    v.x *= inv; v.y *= inv; v.z *= inv; v.w *= inv;
    uint32_t p0, p1;
    asm("cvt.rn.bf16x2.f32 %0, %1, %2;" : "=r"(p0) : "f"(v.y), "f"(v.x));
    asm("cvt.rn.bf16x2.f32 %0, %1, %2;" : "=r"(p1) : "f"(v.w), "f"(v.z));
    reinterpret_cast<uint2*>(Wb + row * 512)[threadIdx.x] = make_uint2(p0, p1);
}

// ---------------- avg_attn from bf16 W ---------------------------------------
__global__ __launch_bounds__(256) void avg_part_kernel(const unsigned* __restrict__ Wb,
                                                       float* __restrict__ ap) {
    int m2 = blockIdx.x * 256 + threadIdx.x;   // column-pair index
    int lc = blockIdx.y;
    int bh = blockIdx.z;
    const unsigned* p = Wb + (long long)bh * LL * (LL / 2) +
                        (long long)lc * 128 * (LL / 2) + m2;
    float s0 = 0.f, s1 = 0.f;
#pragma unroll 8
    for (int l = 0; l < 128; l++) {
        unsigned u = p[(long long)l * (LL / 2)];
        s0 += __uint_as_float(u << 16);
        s1 += __uint_as_float(u & 0xffff0000u);
    }
    float* dst = ap + ((bh * 8 + lc) * LL) + 2 * m2;
    dst[0] = s0;
    dst[1] = s1;
}

__global__ __launch_bounds__(256) void avg_final_kernel(const float* __restrict__ ap,
                                                        float* __restrict__ out) {
    int m = blockIdx.x * 256 + threadIdx.x;
    int b = blockIdx.y;
    float s = 0.f;
#pragma unroll
    for (int h = 0; h < HH; h++)
#pragma unroll
        for (int lc = 0; lc < 8; lc++)
            s += ap[((b * HH + h) * 8 + lc) * LL + m];
    out[BB * EE + b * LL + m] = s * (1.f / (HH * (float)LL));
}

// ---------------- LayerNorm ---------------------------------------------------
__global__ __launch_bounds__(256) void ln_kernel(const float* __restrict__ h,
                                                 const float* __restrict__ gamma,
                                                 const float* __restrict__ beta,
                                                 float* __restrict__ hn) {
    __shared__ float sm[32];
    long long row = blockIdx.x;
    const float* p = h + row * (long long)EE;
    float4 v = reinterpret_cast<const float4*>(p)[threadIdx.x];
    float s = v.x + v.y + v.z + v.w;
    s = blk_reduce_sum(s, sm);
    float mean = s * (1.f / EE);
    float dx = v.x - mean, dy = v.y - mean, dz = v.z - mean, dw = v.w - mean;
    float sq = dx * dx + dy * dy + dz * dz + dw * dw;
    sq = blk_reduce_sum(sq, sm);
    float r = rsqrtf(sq * (1.f / EE) + EPS);
    float4 gm = reinterpret_cast<const float4*>(gamma)[threadIdx.x];
    float4 bt = reinterpret_cast<const float4*>(beta)[threadIdx.x];
    float4 o;
    o.x = dx * r * gm.x + bt.x;
    o.y = dy * r * gm.y + bt.y;
    o.z = dz * r * gm.z + bt.z;
    o.w = dw * r * gm.w + bt.w;
    reinterpret_cast<float4*>(hn + row * (long long)EE)[threadIdx.x] = o;
}

// ---------------- pooled mean -------------------------------------------------
__global__ __launch_bounds__(256) void pooled_part_kernel(const float* __restrict__ hn,
                                                          float* __restrict__ pp) {
    int e = blockIdx.x * 256 + threadIdx.x;
    int lc = blockIdx.y;
    int b = blockIdx.z;
    const float* p = hn + ((long long)b * LL + lc * 128) * EE + e;
    float s = 0.f;
#pragma unroll 8
    for (int l = 0; l < 128; l++) s += p[(long long)l * EE];
    pp[(b * 8 + lc) * EE + e] = s;
}

__global__ __launch_bounds__(256) void pooled_final_kernel(const float* __restrict__ pp,
                                                           float* __restrict__ out) {
    int e = blockIdx.x * 256 + threadIdx.x;
    int b = blockIdx.y;
    float s = 0.f;
#pragma unroll
    for (int lc = 0; lc < 8; lc++) s += pp[(b * 8 + lc) * EE + e];
    out[b * EE + e] = s * (1.f / (float)LL);
}

// ---------------- launch -----------------------------------------------------
extern "C" void kernel_launch(void* const* d_in, const int* in_sizes, int n_in,
                              void* d_out, int out_size) {
    const float* x     = (const float*)d_in[0];
    const float* w_qkv = (const float*)d_in[1];
    const float* b_qkv = (const float*)d_in[2];
    const float* w_out = (const float*)d_in[3];
    const float* b_out = (const float*)d_in[4];
    const float* gamma = (const float*)d_in[5];
    const float* beta  = (const float*)d_in[6];
    float* out = (float*)d_out;

    uint2 *qkvc, *vtc, *ctxc, *xc, *wqc, *woc;
    unsigned* wb;
    float *S, *res, *hn, *ap, *pp;
    cudaGetSymbolAddress((void**)&qkvc, g_qkvc);
    cudaGetSymbolAddress((void**)&S,    g_S);
    cudaGetSymbolAddress((void**)&wb,   g_wb);
    cudaGetSymbolAddress((void**)&vtc,  g_vtc);
    cudaGetSymbolAddress((void**)&ctxc, g_ctxc);
    cudaGetSymbolAddress((void**)&xc,   g_xc);
    cudaGetSymbolAddress((void**)&wqc,  g_wqc);
    cudaGetSymbolAddress((void**)&woc,  g_woc);
    cudaGetSymbolAddress((void**)&res,  g_res);
    cudaGetSymbolAddress((void**)&hn,   g_hn);
    cudaGetSymbolAddress((void**)&ap,   g_avgpart);
    cudaGetSymbolAddress((void**)&pp,   g_poolpart);

    const int M = BB * LL;  // 8192
    constexpr int KPS = 12;
    const int SM_SPLIT128 = 2 * (128 * KPS * 8) + 2 * (128 * KPS * 8);  // 49152
    const int SM_HI64     = 2 * (128 * KPS * 4) + 2 * (64 * KPS * 8);   // 24576
    cudaFuncSetAttribute((const void*)cgemm<128, true, true>,
                         cudaFuncAttributeMaxDynamicSharedMemorySize, SM_SPLIT128);
    cudaFuncSetAttribute((const void*)cgemm<128, true, false>,
                         cudaFuncAttributeMaxDynamicSharedMemorySize, SM_SPLIT128);
    cudaFuncSetAttribute((const void*)cgemm<64, false, true>,
                         cudaFuncAttributeMaxDynamicSharedMemorySize, SM_HI64);

    // 0) pre-split inputs to bf16 cells
    split_kernel<<<512, 256>>>((const float2*)x, xc, BB * LL * EE / 2);
    split_kernel<<<512, 256>>>((const float2*)w_qkv, wqc, E3 * EE / 2);
    split_kernel<<<256, 256>>>((const float2*)w_out, woc, EE * EE / 2);

    // 1) QKV projection -> qkv cells (8192 x 3072 x 1024)
    {
        dim3 grid(E3 / 128, M / 128, 1);
        cgemm<128, true, true><<<grid, 256, SM_SPLIT128>>>(
            xc, wqc, (float*)qkvc, b_qkv, nullptr,
            EE, EE / 2, EE / 2, E3,
            0, 0, 0, 0, 0, 0, 1, 1.0f);
    }

    // 1b) Vt cells
    {
        dim3 grid(LL / 32, DD / 32, BB * HH);
        vtrans_kernel<<<grid, 256>>>(qkvc, vtc);
    }

    // 2) scores -> S fp32 (1024x1024x64, 128 batches)
    {
        dim3 grid(LL / 128, LL / 128, BB * HH);
        cgemm<128, true, false><<<grid, 256, SM_SPLIT128>>>(
            qkvc /*Q*/, qkvc + EE / 2 /*K*/, S, nullptr, nullptr,
            DD, E3 / 2, E3 / 2, LL,
            (long long)LL * E3 / 2, DD / 2,
            (long long)LL * E3 / 2, DD / 2,
            (long long)HH * LL * LL, (long long)LL * LL,
            HH, 0.125f);
    }

    // 3) softmax -> W bf16
    softmax_kernel<<<BB * HH * LL, 256>>>(S, wb);

    // 4) avg_attn
    {
        dim3 g1(LL / 512, 8, BB * HH);
        avg_part_kernel<<<g1, 256>>>(wb, ap);
        dim3 g2(LL / 256, BB);
        avg_final_kernel<<<g2, 256>>>(ap, out);
    }

    // 5) ctx = W(bf16 hi) @ Vt^T -> ctx cells (1024 x 64 x 1024, 128 batches)
    //    A strides in uint cells: per-b = HH*LL*LL/2, per-h = LL*LL/2
    {
        dim3 grid(1, LL / 128, BB * HH);
        cgemm<64, false, true><<<grid, 256, SM_HI64>>>(
            wb, vtc, (float*)ctxc, nullptr, nullptr,
            LL, LL / 2, LL / 2, EE,
            (long long)HH * LL * LL / 2, (long long)LL * LL / 2,
            (long long)HH * DD * LL / 2, (long long)DD * LL / 2,
            (long long)LL * EE, (long long)DD,
            HH, 1.0f);
    }

    // 6) out proj + bias + residual -> res fp32
    {
        dim3 grid(EE / 128, M / 128, 1);
        cgemm<128, true, false><<<grid, 256, SM_SPLIT128>>>(
            ctxc, woc, res, b_out, x,
            EE, EE / 2, EE / 2, EE,
            0, 0, 0, 0, 0, 0, 1, 1.0f);
    }

    // 7) layernorm
    ln_kernel<<<M, 256>>>(res, gamma, beta, hn);

    // 8) pooled mean
    {
        dim3 g1(EE / 256, 8, BB);
        pooled_part_kernel<<<g1, 256>>>(hn, pp);
        dim3 g2(EE / 256, BB);
        pooled_final_kernel<<<g2, 256>>>(pp, out);
    }
}

// round 12
// speedup vs baseline: 3.2595x; 1.1145x over previous
#include <cuda_runtime.h>
#include <cuda_bf16.h>
#include <math.h>
#include <stdint.h>

// Problem dims (fixed)
#define BB 8
#define LL 1024
#define EE 1024
#define HH 16
#define DD 64
#define E3 3072
#define EPS 1e-5f

// ---------------- scratch (device globals; no allocation allowed) ----------
// "cell" = uint2 {hi_bf16x2, lo_bf16x2} for a pair of consecutive-K fp32 values.
__device__ __align__(128) uint2 g_qkvc[BB * LL * E3 / 2];               // 100 MB
__device__ float g_S[(size_t)BB * HH * LL * LL];                         // 512 MB
__device__ __align__(128) unsigned g_wb[(size_t)BB * HH * LL * LL / 2];  // W bf16 hi, 256 MB
__device__ __align__(128) uint2 g_vtc[BB * HH * DD * LL / 2];            // Vt cells, 32 MB
__device__ __align__(128) uint2 g_ctxc[BB * LL * EE / 2];                // ctx cells, 32 MB
__device__ __align__(128) uint2 g_xc[BB * LL * EE / 2];                  // x cells, 32 MB
__device__ __align__(128) uint2 g_wqc[E3 * EE / 2];                      // w_qkv cells, 12 MB
__device__ __align__(128) uint2 g_woc[EE * EE / 2];                      // w_out cells, 4 MB
__device__ float g_res[BB * LL * EE];                                    // 32 MB
__device__ float g_hn[BB * LL * EE];                                     // 32 MB
__device__ float g_avgpart[BB * HH * 8 * LL];
__device__ float g_poolpart[BB * 8 * EE];

// ---------------- helpers ----------------------------------------------------
__device__ __forceinline__ uint2 split2(float x0, float x1) {
    uint32_t hp, lp;
    asm("cvt.rn.bf16x2.f32 %0, %1, %2;" : "=r"(hp) : "f"(x1), "f"(x0));
    float h0 = __uint_as_float(hp << 16);
    float h1 = __uint_as_float(hp & 0xffff0000u);
    float l0 = x0 - h0;
    float l1 = x1 - h1;
    asm("cvt.rn.bf16x2.f32 %0, %1, %2;" : "=r"(lp) : "f"(l1), "f"(l0));
    return make_uint2(hp, lp);
}

__device__ __forceinline__ void mma16(float* d, const uint32_t* a, const uint32_t* b) {
    asm volatile(
        "mma.sync.aligned.m16n8k16.row.col.f32.bf16.bf16.f32 "
        "{%0,%1,%2,%3}, {%4,%5,%6,%7}, {%8,%9}, {%0,%1,%2,%3};"
        : "+f"(d[0]), "+f"(d[1]), "+f"(d[2]), "+f"(d[3])
        : "r"(a[0]), "r"(a[1]), "r"(a[2]), "r"(a[3]), "r"(b[0]), "r"(b[1]));
}

__device__ __forceinline__ void cp16(uint32_t dst, const void* src) {
    asm volatile("cp.async.cg.shared.global [%0], [%1], 16;"
                 :: "r"(dst), "l"(__cvta_generic_to_global(src)) : "memory");
}
__device__ __forceinline__ void cp_commit() {
    asm volatile("cp.async.commit_group;" ::: "memory");
}
template <int N>
__device__ __forceinline__ void cp_wait() {
    asm volatile("cp.async.wait_group %0;" :: "n"(N) : "memory");
}

// ---------------- pre-split kernel: fp32 -> cells ----------------------------
__global__ __launch_bounds__(256) void split_kernel(const float2* __restrict__ src,
                                                    uint2* __restrict__ dst, int n) {
    int i = blockIdx.x * 256 + threadIdx.x;
    int stride = gridDim.x * 256;
    for (; i < n; i += stride) {
        float2 v = src[i];
        dst[i] = split2(v.x, v.y);
    }
}

// ---------------- cp.async bf16-cell tensor-core GEMM ------------------------
// C[128*gy, TN*gx] = alpha * A(M,K) * B(N,K)^T (+bias) (+resid)
// A: ASPLIT ? uint2 cells (3-term) : uint hi-cells (2-term). B: uint2 cells.
// ld*C in cells (= K_fp32/2). OUTC: write C as split cells (else fp32).
// Batched via blockIdx.z = bo*inner + bi (A/B strides in cells, C in fp32).
// 3-stage cp.async ring, one __syncthreads per K16 chunk, 2 CTAs/SM.
template <int TN, bool ASPLIT, bool OUTC>
__global__ __launch_bounds__(256, 2) void cgemm(
    const void* __restrict__ Ap_, const uint2* __restrict__ Bp,
    float* __restrict__ C,
    const float* __restrict__ bias, const float* __restrict__ resid,
    int K, int ldaC, int ldbC, int ldc,
    long long sAo, long long sAi, long long sBo, long long sBi,
    long long sCo, long long sCi, int inner, float alpha)
{
    extern __shared__ __align__(16) char sm[];
    constexpr int KPS = 12;                        // 8 cells + 4 pad
    constexpr int ABYTES = ASPLIT ? 128 * KPS * 8 : 128 * KPS * 4;
    constexpr int BBYTES = TN * KPS * 8;
    constexpr int SLOT = ABYTES + BBYTES;

    const int tid = threadIdx.x;
    const int warp = tid >> 5, lane = tid & 31;
    const int g = lane >> 2, tg = lane & 3;

    int bz = blockIdx.z;
    int bo = bz / inner, bi = bz % inner;
    long long aoff = bo * sAo + bi * sAi;
    Bp += bo * sBo + bi * sBi;
    long long coff = bo * sCo + bi * sCi;
    C += coff;
    const float* Rp = resid ? resid + coff : nullptr;

    const int bm = blockIdx.y * 128;
    const int bn = blockIdx.x * TN;

    constexpr int WN = TN / 4;        // 32 or 16
    constexpr int MT = 4;
    constexpr int NTL = WN / 8;       // 4 or 2
    const int wm = (warp >> 2) * 64;
    const int wn = (warp & 3) * WN;

    float acc[MT][NTL][4];
#pragma unroll
    for (int i = 0; i < MT; i++)
#pragma unroll
        for (int j = 0; j < NTL; j++)
#pragma unroll
            for (int q = 0; q < 4; q++) acc[i][j][q] = 0.f;

    uint32_t sb;
    asm("{ .reg .u64 t; cvta.to.shared.u64 t, %1; cvt.u32.u64 %0, t; }"
        : "=r"(sb) : "l"(sm));

    // ---- precomputed staging pointers (advance by 8 elems per chunk)
    const int r0 = tid >> 2, j4 = tid & 3;        // 64-row groups, 16B chunk
    const int r1 = tid >> 1, j2 = tid & 1;        // 128 rows, 16B chunk (hi-only A)
    const uint2* aS0;
    const uint2* aS1;
    const unsigned* aH;
    if (ASPLIT) {
        const uint2* A2 = (const uint2*)Ap_ + aoff;
        aS0 = A2 + (long long)(bm + r0) * ldaC + 2 * j4;
        aS1 = A2 + (long long)(bm + r0 + 64) * ldaC + 2 * j4;
        aH = nullptr;
    } else {
        const unsigned* A1 = (const unsigned*)Ap_ + aoff;
        aH = A1 + (long long)(bm + r1) * ldaC + 4 * j2;
        aS0 = aS1 = nullptr;
    }
    const uint2* bS0 = Bp + (long long)(bn + r0) * ldbC + 2 * j4;
    const uint2* bS1 = (TN == 128) ? Bp + (long long)(bn + r0 + 64) * ldbC + 2 * j4
                                   : nullptr;
    const uint32_t aD0 = ASPLIT ? (uint32_t)(r0 * (KPS * 8) + 16 * j4)
                                : (uint32_t)(r1 * (KPS * 4) + 16 * j2);
    const uint32_t aD1 = ASPLIT ? (uint32_t)((r0 + 64) * (KPS * 8) + 16 * j4) : 0;
    const uint32_t bD0 = (uint32_t)(ABYTES + r0 * (KPS * 8) + 16 * j4);
    const uint32_t bD1 = (uint32_t)(ABYTES + (r0 + 64) * (KPS * 8) + 16 * j4);

    const int nc = K / 16;

    auto stage = [&](int c, int slot) {
        uint32_t base = sb + slot * SLOT;
        if (ASPLIT) {
            cp16(base + aD0, aS0 + c * 8);
            cp16(base + aD1, aS1 + c * 8);
        } else {
            cp16(base + aD0, aH + c * 8);
        }
        cp16(base + bD0, bS0 + c * 8);
        if (TN == 128) cp16(base + bD1, bS1 + c * 8);
    };

    stage(0, 0); cp_commit();
    stage(1, 1); cp_commit();

    int slot = 0;
    for (int c = 0; c < nc; c++) {
        if (c + 1 < nc) cp_wait<1>();
        else            cp_wait<0>();
        __syncthreads();
        {
            int ns = slot + 2; if (ns >= 3) ns -= 3;
            if (c + 2 < nc) { stage(c + 2, ns); cp_commit(); }
        }

        const char* slotbase = sm + slot * SLOT;
        const uint2* bs = (const uint2*)(slotbase + ABYTES);
        uint2 bfr[NTL][2];
#pragma unroll
        for (int nt = 0; nt < NTL; nt++) {
            int c0 = wn + nt * 8 + g;
            bfr[nt][0] = bs[c0 * KPS + tg];
            bfr[nt][1] = bs[c0 * KPS + tg + 4];
        }

        if (ASPLIT) {
            const uint2* as = (const uint2*)slotbase;
#pragma unroll
            for (int mt = 0; mt < MT; mt++) {
                int rr = wm + mt * 16 + g;
                uint2 f0 = as[rr * KPS + tg];
                uint2 f1 = as[(rr + 8) * KPS + tg];
                uint2 f2 = as[rr * KPS + tg + 4];
                uint2 f3 = as[(rr + 8) * KPS + tg + 4];
                uint32_t ah[4] = {f0.x, f1.x, f2.x, f3.x};
                uint32_t al[4] = {f0.y, f1.y, f2.y, f3.y};
#pragma unroll
                for (int nt = 0; nt < NTL; nt++) {
                    uint32_t bh[2] = {bfr[nt][0].x, bfr[nt][1].x};
                    uint32_t bl[2] = {bfr[nt][0].y, bfr[nt][1].y};
                    mma16(acc[mt][nt], ah, bh);
                    mma16(acc[mt][nt], ah, bl);
                    mma16(acc[mt][nt], al, bh);
                }
            }
        } else {
            const unsigned* as = (const unsigned*)slotbase;
#pragma unroll
            for (int mt = 0; mt < MT; mt++) {
                int rr = wm + mt * 16 + g;
                uint32_t ah[4];
                ah[0] = as[rr * KPS + tg];
                ah[1] = as[(rr + 8) * KPS + tg];
                ah[2] = as[rr * KPS + tg + 4];
                ah[3] = as[(rr + 8) * KPS + tg + 4];
#pragma unroll
                for (int nt = 0; nt < NTL; nt++) {
                    uint32_t bh[2] = {bfr[nt][0].x, bfr[nt][1].x};
                    uint32_t bl[2] = {bfr[nt][0].y, bfr[nt][1].y};
                    mma16(acc[mt][nt], ah, bh);
                    mma16(acc[mt][nt], ah, bl);
                }
            }
        }
        slot = (slot == 2) ? 0 : slot + 1;
        __syncthreads();  // NOTE: single barrier per chunk lives at loop top via
                          // cp_wait + this; see hazard analysis in commit msg.
    }

    // ---- epilogue
#pragma unroll
    for (int mt = 0; mt < MT; mt++) {
#pragma unroll
        for (int nt = 0; nt < NTL; nt++) {
            int c = bn + wn + nt * 8 + 2 * tg;
#pragma unroll
            for (int hrow = 0; hrow < 2; hrow++) {
                int gr = bm + wm + mt * 16 + g + hrow * 8;
                float vx = acc[mt][nt][2 * hrow] * alpha;
                float vy = acc[mt][nt][2 * hrow + 1] * alpha;
                if (bias) { vx += bias[c]; vy += bias[c + 1]; }
                long long ci = (long long)gr * ldc + c;
                if (Rp) {
                    float2 rr = *reinterpret_cast<const float2*>(&Rp[ci]);
                    vx += rr.x; vy += rr.y;
                }
                if (OUTC) {
                    reinterpret_cast<uint2*>(C)[ci >> 1] = split2(vx, vy);
                } else {
                    float2 o; o.x = vx; o.y = vy;
                    *reinterpret_cast<float2*>(&C[ci]) = o;
                }
            }
        }
    }
}

// ---------------- V transpose (cells -> transposed cells) --------------------
__global__ __launch_bounds__(256) void vtrans_kernel(const uint2* __restrict__ qc,
                                                     uint2* __restrict__ vt) {
    __shared__ ushort hiS[32][33];
    __shared__ ushort loS[32][33];
    int bh = blockIdx.z;
    int b = bh >> 4, h = bh & 15;
    int lb = blockIdx.x * 32, db = blockIdx.y * 32;
    int t = threadIdx.x;
    int l = t >> 3, cj = t & 7;
#pragma unroll
    for (int p = 0; p < 2; p++) {
        int j = cj + 8 * p;  // local d-cell 0..15
        long long idx = (long long)(b * LL + lb + l) * (E3 / 2) + 1024 + h * 32 + (db >> 1) + j;
        uint2 cell = qc[idx];
        hiS[l][2 * j]     = (ushort)(cell.x & 0xffffu);
        hiS[l][2 * j + 1] = (ushort)(cell.x >> 16);
        loS[l][2 * j]     = (ushort)(cell.y & 0xffffu);
        loS[l][2 * j + 1] = (ushort)(cell.y >> 16);
    }
    __syncthreads();
    int d = t >> 3;
#pragma unroll
    for (int p = 0; p < 2; p++) {
        int jj = cj + 8 * p;  // local l-pair 0..15
        uint2 cell;
        cell.x = (uint32_t)hiS[2 * jj][d] | ((uint32_t)hiS[2 * jj + 1][d] << 16);
        cell.y = (uint32_t)loS[2 * jj][d] | ((uint32_t)loS[2 * jj + 1][d] << 16);
        long long dst = (long long)bh * (DD * LL / 2) + (long long)(db + d) * (LL / 2) + (lb >> 1) + jj;
        vt[dst] = cell;
    }
}

// ---------------- block reductions -----------------------------------------
__device__ __forceinline__ float blk_reduce_sum(float v, float* sm) {
#pragma unroll
    for (int o = 16; o > 0; o >>= 1) v += __shfl_xor_sync(0xffffffffu, v, o);
    int w = threadIdx.x >> 5;
    if ((threadIdx.x & 31) == 0) sm[w] = v;
    __syncthreads();
    if (threadIdx.x == 0) {
        float s = 0.f;
        int nw = blockDim.x >> 5;
        for (int i = 0; i < nw; i++) s += sm[i];
        sm[0] = s;
    }
    __syncthreads();
    float r = sm[0];
    __syncthreads();
    return r;
}

__device__ __forceinline__ float blk_reduce_max(float v, float* sm) {
#pragma unroll
    for (int o = 16; o > 0; o >>= 1)
        v = fmaxf(v, __shfl_xor_sync(0xffffffffu, v, o));
    int w = threadIdx.x >> 5;
    if ((threadIdx.x & 31) == 0) sm[w] = v;
    __syncthreads();
    if (threadIdx.x == 0) {
        float s = sm[0];
        int nw = blockDim.x >> 5;
        for (int i = 1; i < nw; i++) s = fmaxf(s, sm[i]);
        sm[0] = s;
    }
    __syncthreads();
    float r = sm[0];
    __syncthreads();
    return r;
}

// ---------------- softmax: read S fp32, write W bf16 (hi only) ---------------
__global__ __launch_bounds__(256) void softmax_kernel(const float* __restrict__ S,
                                                      unsigned* __restrict__ Wb) {
    __shared__ float sm[32];
    long long row = blockIdx.x;
    const float* p = S + row * (long long)LL;
    float4 v = reinterpret_cast<const float4*>(p)[threadIdx.x];
    float mx = fmaxf(fmaxf(v.x, v.y), fmaxf(v.z, v.w));
    mx = blk_reduce_max(mx, sm);
    v.x = __expf(v.x - mx);
    v.y = __expf(v.y - mx);
    v.z = __expf(v.z - mx);
    v.w = __expf(v.w - mx);
    float s = v.x + v.y + v.z + v.w;
    s = blk_reduce_sum(s, sm);
    float inv = 1.f / s;
    v.x *= inv; v.y *= inv; v.z *= inv; v.w *= inv;
    uint32_t p0, p1;
    asm("cvt.rn.bf16x2.f32 %0, %1, %2;" : "=r"(p0) : "f"(v.y), "f"(v.x));
    asm("cvt.rn.bf16x2.f32 %0, %1, %2;" : "=r"(p1) : "f"(v.w), "f"(v.z));
    reinterpret_cast<uint2*>(Wb + row * 512)[threadIdx.x] = make_uint2(p0, p1);
}

// ---------------- avg_attn from bf16 W ---------------------------------------
__global__ __launch_bounds__(256) void avg_part_kernel(const unsigned* __restrict__ Wb,
                                                       float* __restrict__ ap) {
    int m2 = blockIdx.x * 256 + threadIdx.x;   // column-pair index
    int lc = blockIdx.y;
    int bh = blockIdx.z;
    const unsigned* p = Wb + (long long)bh * LL * (LL / 2) +
                        (long long)lc * 128 * (LL / 2) + m2;
    float s0 = 0.f, s1 = 0.f;
#pragma unroll 8
    for (int l = 0; l < 128; l++) {
        unsigned u = p[(long long)l * (LL / 2)];
        s0 += __uint_as_float(u << 16);
        s1 += __uint_as_float(u & 0xffff0000u);
    }
    float* dst = ap + ((bh * 8 + lc) * LL) + 2 * m2;
    dst[0] = s0;
    dst[1] = s1;
}

__global__ __launch_bounds__(256) void avg_final_kernel(const float* __restrict__ ap,
                                                        float* __restrict__ out) {
    int m = blockIdx.x * 256 + threadIdx.x;
    int b = blockIdx.y;
    float s = 0.f;
#pragma unroll
    for (int h = 0; h < HH; h++)
#pragma unroll
        for (int lc = 0; lc < 8; lc++)
            s += ap[((b * HH + h) * 8 + lc) * LL + m];
    out[BB * EE + b * LL + m] = s * (1.f / (HH * (float)LL));
}

// ---------------- LayerNorm ---------------------------------------------------
__global__ __launch_bounds__(256) void ln_kernel(const float* __restrict__ h,
                                                 const float* __restrict__ gamma,
                                                 const float* __restrict__ beta,
                                                 float* __restrict__ hn) {
    __shared__ float sm[32];
    long long row = blockIdx.x;
    const float* p = h + row * (long long)EE;
    float4 v = reinterpret_cast<const float4*>(p)[threadIdx.x];
    float s = v.x + v.y + v.z + v.w;
    s = blk_reduce_sum(s, sm);
    float mean = s * (1.f / EE);
    float dx = v.x - mean, dy = v.y - mean, dz = v.z - mean, dw = v.w - mean;
    float sq = dx * dx + dy * dy + dz * dz + dw * dw;
    sq = blk_reduce_sum(sq, sm);
    float r = rsqrtf(sq * (1.f / EE) + EPS);
    float4 gm = reinterpret_cast<const float4*>(gamma)[threadIdx.x];
    float4 bt = reinterpret_cast<const float4*>(beta)[threadIdx.x];
    float4 o;
    o.x = dx * r * gm.x + bt.x;
    o.y = dy * r * gm.y + bt.y;
    o.z = dz * r * gm.z + bt.z;
    o.w = dw * r * gm.w + bt.w;
    reinterpret_cast<float4*>(hn + row * (long long)EE)[threadIdx.x] = o;
}

// ---------------- pooled mean -------------------------------------------------
__global__ __launch_bounds__(256) void pooled_part_kernel(const float* __restrict__ hn,
                                                          float* __restrict__ pp) {
    int e = blockIdx.x * 256 + threadIdx.x;
    int lc = blockIdx.y;
    int b = blockIdx.z;
    const float* p = hn + ((long long)b * LL + lc * 128) * EE + e;
    float s = 0.f;
#pragma unroll 8
    for (int l = 0; l < 128; l++) s += p[(long long)l * EE];
    pp[(b * 8 + lc) * EE + e] = s;
}

__global__ __launch_bounds__(256) void pooled_final_kernel(const float* __restrict__ pp,
                                                           float* __restrict__ out) {
    int e = blockIdx.x * 256 + threadIdx.x;
    int b = blockIdx.y;
    float s = 0.f;
#pragma unroll
    for (int lc = 0; lc < 8; lc++) s += pp[(b * 8 + lc) * EE + e];
    out[b * EE + e] = s * (1.f / (float)LL);
}

// ---------------- launch -----------------------------------------------------
extern "C" void kernel_launch(void* const* d_in, const int* in_sizes, int n_in,
                              void* d_out, int out_size) {
    const float* x     = (const float*)d_in[0];
    const float* w_qkv = (const float*)d_in[1];
    const float* b_qkv = (const float*)d_in[2];
    const float* w_out = (const float*)d_in[3];
    const float* b_out = (const float*)d_in[4];
    const float* gamma = (const float*)d_in[5];
    const float* beta  = (const float*)d_in[6];
    float* out = (float*)d_out;

    uint2 *qkvc, *vtc, *ctxc, *xc, *wqc, *woc;
    unsigned* wb;
    float *S, *res, *hn, *ap, *pp;
    cudaGetSymbolAddress((void**)&qkvc, g_qkvc);
    cudaGetSymbolAddress((void**)&S,    g_S);
    cudaGetSymbolAddress((void**)&wb,   g_wb);
    cudaGetSymbolAddress((void**)&vtc,  g_vtc);
    cudaGetSymbolAddress((void**)&ctxc, g_ctxc);
    cudaGetSymbolAddress((void**)&xc,   g_xc);
    cudaGetSymbolAddress((void**)&wqc,  g_wqc);
    cudaGetSymbolAddress((void**)&woc,  g_woc);
    cudaGetSymbolAddress((void**)&res,  g_res);
    cudaGetSymbolAddress((void**)&hn,   g_hn);
    cudaGetSymbolAddress((void**)&ap,   g_avgpart);
    cudaGetSymbolAddress((void**)&pp,   g_poolpart);

    const int M = BB * LL;  // 8192
    constexpr int KPS = 12;
    const int SM_SPLIT128 = 3 * (128 * KPS * 8 + 128 * KPS * 8);  // 73728
    const int SM_HI64     = 3 * (128 * KPS * 4 + 64 * KPS * 8);   // 36864
    cudaFuncSetAttribute((const void*)cgemm<128, true, true>,
                         cudaFuncAttributeMaxDynamicSharedMemorySize, SM_SPLIT128);
    cudaFuncSetAttribute((const void*)cgemm<128, true, false>,
                         cudaFuncAttributeMaxDynamicSharedMemorySize, SM_SPLIT128);
    cudaFuncSetAttribute((const void*)cgemm<64, false, true>,
                         cudaFuncAttributeMaxDynamicSharedMemorySize, SM_HI64);

    // 0) pre-split inputs to bf16 cells
    split_kernel<<<512, 256>>>((const float2*)x, xc, BB * LL * EE / 2);
    split_kernel<<<512, 256>>>((const float2*)w_qkv, wqc, E3 * EE / 2);
    split_kernel<<<256, 256>>>((const float2*)w_out, woc, EE * EE / 2);

    // 1) QKV projection -> qkv cells (8192 x 3072 x 1024)
    {
        dim3 grid(E3 / 128, M / 128, 1);
        cgemm<128, true, true><<<grid, 256, SM_SPLIT128>>>(
            xc, wqc, (float*)qkvc, b_qkv, nullptr,
            EE, EE / 2, EE / 2, E3,
            0, 0, 0, 0, 0, 0, 1, 1.0f);
    }

    // 1b) Vt cells
    {
        dim3 grid(LL / 32, DD / 32, BB * HH);
        vtrans_kernel<<<grid, 256>>>(qkvc, vtc);
    }

    // 2) scores -> S fp32 (1024x1024x64, 128 batches)
    {
        dim3 grid(LL / 128, LL / 128, BB * HH);
        cgemm<128, true, false><<<grid, 256, SM_SPLIT128>>>(
            qkvc /*Q*/, qkvc + EE / 2 /*K*/, S, nullptr, nullptr,
            DD, E3 / 2, E3 / 2, LL,
            (long long)LL * E3 / 2, DD / 2,
            (long long)LL * E3 / 2, DD / 2,
            (long long)HH * LL * LL, (long long)LL * LL,
            HH, 0.125f);
    }

    // 3) softmax -> W bf16
    softmax_kernel<<<BB * HH * LL, 256>>>(S, wb);

    // 4) avg_attn
    {
        dim3 g1(LL / 512, 8, BB * HH);
        avg_part_kernel<<<g1, 256>>>(wb, ap);
        dim3 g2(LL / 256, BB);
        avg_final_kernel<<<g2, 256>>>(ap, out);
    }

    // 5) ctx = W(bf16 hi) @ Vt^T -> ctx cells (1024 x 64 x 1024, 128 batches)
    {
        dim3 grid(1, LL / 128, BB * HH);
        cgemm<64, false, true><<<grid, 256, SM_HI64>>>(
            wb, vtc, (float*)ctxc, nullptr, nullptr,
            LL, LL / 2, LL / 2, EE,
            (long long)HH * LL * LL / 2, (long long)LL * LL / 2,
            (long long)HH * DD * LL / 2, (long long)DD * LL / 2,
            (long long)LL * EE, (long long)DD,
            HH, 1.0f);
    }

    // 6) out proj + bias + residual -> res fp32
    {
        dim3 grid(EE / 128, M / 128, 1);
        cgemm<128, true, false><<<grid, 256, SM_SPLIT128>>>(
            ctxc, woc, res, b_out, x,
            EE, EE / 2, EE / 2, EE,
            0, 0, 0, 0, 0, 0, 1, 1.0f);
    }

    // 7) layernorm
    ln_kernel<<<M, 256>>>(res, gamma, beta, hn);

    // 8) pooled mean
    {
        dim3 g1(EE / 256, 8, BB);
        pooled_part_kernel<<<g1, 256>>>(hn, pp);
        dim3 g2(EE / 256, BB);
        pooled_final_kernel<<<g2, 256>>>(pp, out);
    }
}